// round 5
// baseline (speedup 1.0000x reference)
#include <cuda_runtime.h>
#include <math.h>

#define HH 384
#define WW 384
#define NPIX (HH*WW)          // 147456
#define BB 2
#define BN (BB*NPIX)          // 294912
#define NDIR 128
#define SEG 48

// ======================= scratch buffers =======================
__device__ float g_P[BN];
__device__ float g_E[BN];
__device__ float g_S[BN];
__device__ float g_Lp[BN];
__device__ float g_zb[BN];
__device__ float g_Ra[2*BN];     // [(b*2+k)*NPIX+n]
__device__ float g_DM[BN];
__device__ float g_t0[2*BN], g_t1[2*BN], g_t2[2*BN];
__device__ float g_lla[2*BN];
__device__ float g_den[2*BN];
__device__ float g_gld[2*BN];
__device__ float g_La[BN];
__device__ unsigned char g_idxb[BN];
__device__ float g_colsum[(size_t)4*NPIX*32];   // [bk][y][x][bin] (bin-prefix form)

// ======================= small state =======================
__device__ float    g_sv[64];
__device__ unsigned g_mm[BB][2] = {{0xFFFFFFFFu,0u},{0xFFFFFFFFu,0u}};
__device__ double   g_reg[BB][5];
__device__ double   g_beta[BB][2];
__device__ double   g_cacc[BB][9];
__device__ double   g_mean3[BB][3];
__device__ double   g_wwh[BB][9];
__device__ float    g_cdir[BB*NDIR*3];
__device__ float    g_cbest[BB][3];
__device__ double   g_dirm[BB][NDIR][4];
__device__ double   g_clacc[BB][2][10];
__device__ double   g_clmu[BB][2][3];
__device__ double   g_clinv[BB][2][9];
__device__ double   g_ghist[BB][2][32];
__device__ float    g_gcdf[BB][2][32];
__device__ double   g_esinv[BB][6];   // i00 i01 i11 meanE meanS

// ======================= helpers =======================
static __device__ __forceinline__ unsigned f2u(float f){
    unsigned u = __float_as_uint(f);
    return (u & 0x80000000u) ? ~u : (u | 0x80000000u);
}
static __device__ __forceinline__ float u2f(unsigned u){
    unsigned v = (u & 0x80000000u) ? (u & 0x7FFFFFFFu) : ~u;
    return __uint_as_float(v);
}
static __device__ __forceinline__ float softplusf(float x){
    float t = log1pf(expf(-fabsf(x)));
    return x >= 0.f ? x + t : t;
}
static __device__ double blockReduceD(double v){
    __shared__ double sh[32];
    int lane = threadIdx.x & 31, wid = threadIdx.x >> 5;
    for (int o=16;o;o>>=1) v += __shfl_down_sync(0xffffffffu, v, o);
    if (lane==0) sh[wid] = v;
    __syncthreads();
    int nw = (blockDim.x + 31) >> 5;
    v = (threadIdx.x < nw) ? sh[threadIdx.x] : 0.0;
    if (wid==0) for (int o=16;o;o>>=1) v += __shfl_down_sync(0xffffffffu, v, o);
    __syncthreads();
    return v;
}
static __device__ void eigh3(const double* A, double* e, double* V){
    double a[9]; for(int i=0;i<9;i++) a[i]=A[i];
    for(int i=0;i<9;i++) V[i] = (i%4==0)?1.0:0.0;
    for(int sweep=0;sweep<40;sweep++){
        double off = fabs(a[1])+fabs(a[2])+fabs(a[5]);
        if(off < 1e-300) break;
        for(int p=0;p<2;p++) for(int q=p+1;q<3;q++){
            double apq=a[p*3+q];
            if(fabs(apq) < 1e-300) continue;
            double app=a[p*3+p], aqq=a[q*3+q];
            double th=(aqq-app)/(2.0*apq);
            double t=(th>=0?1.0:-1.0)/(fabs(th)+sqrt(th*th+1.0));
            double c=1.0/sqrt(t*t+1.0), s=t*c;
            for(int i=0;i<3;i++){ double x=a[i*3+p],y=a[i*3+q]; a[i*3+p]=c*x-s*y; a[i*3+q]=s*x+c*y; }
            for(int i=0;i<3;i++){ double x=a[p*3+i],y=a[q*3+i]; a[p*3+i]=c*x-s*y; a[q*3+i]=s*x+c*y; }
            for(int i=0;i<3;i++){ double x=V[i*3+p],y=V[i*3+q]; V[i*3+p]=c*x-s*y; V[i*3+q]=s*x+c*y; }
        }
    }
    e[0]=a[0]; e[1]=a[4]; e[2]=a[8];
}
static __device__ void inv3(const double* m, double* inv){
    double a=m[0],b=m[1],c=m[2],d=m[3],e=m[4],f=m[5],g=m[6],h=m[7],i=m[8];
    double A=e*i-f*h, B=c*h-b*i, C=b*f-c*e;
    double D=f*g-d*i, E=a*i-c*g, F=c*d-a*f;
    double G=d*h-e*g, Hh=b*g-a*h, I=a*e-b*d;
    double det=a*A+b*D+c*G, id=1.0/det;
    inv[0]=A*id; inv[1]=B*id; inv[2]=C*id;
    inv[3]=D*id; inv[4]=E*id; inv[5]=F*id;
    inv[6]=G*id; inv[7]=Hh*id; inv[8]=I*id;
}

// ======================= fused radix select =======================
// jobs: {kind, type, b, rank, slotA, slotB}
// kind 0 = median (rank) -> slotA, then MAD (median of |x-med|) -> slotB
// kind 1 = value at rank -> slotA, value at rank+1 -> slotB
__device__ const int g_seljobs[22*6] = {
 // phase A (base 0): med+MAD of Lp,E,S per batch
 0,0,0,73727,0,6,   0,1,0,73727,1,7,   0,2,0,73727,2,8,
 0,0,1,73727,3,9,   0,1,1,73727,4,10,  0,2,1,73727,5,11,
 // phase Z (base 6): zb quartile brackets
 1,3,0,36863,12,13,  1,3,0,110591,14,15,  1,3,1,36863,16,17,  1,3,1,110591,18,19,
 // phase L (base 10): LLA med+MAD
 0,4,0,73727,20,24,  0,5,0,73727,21,25,  0,4,1,73727,22,26,  0,5,1,73727,23,27,
 // phase G (base 14): GLD med+MAD
 0,6,0,73727,28,32,  0,7,0,73727,29,33,  0,6,1,73727,30,34,  0,7,1,73727,31,35,
 // phase F (base 18): La 1%/99% brackets
 1,8,0,1474,36,37,  1,8,0,145980,38,39,  1,8,1,1474,40,41,  1,8,1,145980,42,43
};

static __device__ const float* selSrc(int type, int b){
    switch(type){
        case 0: return g_Lp + b*NPIX;
        case 1: return g_E  + b*NPIX;
        case 2: return g_S  + b*NPIX;
        case 3: return g_zb + b*NPIX;
        case 4: return g_lla + (b*2+0)*NPIX;
        case 5: return g_lla + (b*2+1)*NPIX;
        case 6: return g_gld + (b*2+0)*NPIX;
        case 7: return g_gld + (b*2+1)*NPIX;
        default: return g_La + b*NPIX;
    }
}

static __device__ float blockRadixSelect(const float* src, float ref, int useAbs, int rank,
                                         unsigned* shist, unsigned* ppref, int* prank){
    if(threadIdx.x==0){ *ppref=0u; *prank=rank; }
    for(int pass=0; pass<4; pass++){
        int shift = 24 - 8*pass;
        __syncthreads();                       // covers init / previous pick
        for(int i=threadIdx.x;i<256;i+=blockDim.x) shist[i]=0u;
        __syncthreads();
        unsigned pref = *ppref;
        for(int i=threadIdx.x;i<NPIX;i+=blockDim.x){
            float v = src[i]; if(useAbs) v = fabsf(v - ref);
            unsigned key = f2u(v);
            if(pass==0 || (key>>(shift+8)) == (pref>>(shift+8)))
                atomicAdd(&shist[(key>>shift)&255], 1u);
        }
        __syncthreads();
        if(threadIdx.x < 32){
            int lane = threadIdx.x;
            unsigned c8[8]; unsigned s=0u;
            #pragma unroll
            for(int i=0;i<8;i++){ c8[i]=shist[lane*8+i]; s+=c8[i]; }
            unsigned cum=s;
            #pragma unroll
            for(int o=1;o<32;o<<=1){ unsigned t=__shfl_up_sync(0xffffffffu,cum,o); if(lane>=o) cum+=t; }
            unsigned prev=cum-s;
            int rk = *prank;
            __syncwarp();
            if(prev <= (unsigned)rk && (unsigned)rk < cum){
                int rr = rk - (int)prev; int bin = lane*8;
                #pragma unroll
                for(int i=0;i<8;i++){ if(rr < (int)c8[i]){ bin=lane*8+i; break; } rr -= (int)c8[i]; }
                *prank = rr;
                *ppref = pref | ((unsigned)bin << shift);
            }
        }
    }
    __syncthreads();
    return u2f(*ppref);
}

__global__ void selFused(int jobBase){
    __shared__ unsigned shist[256];
    __shared__ unsigned s_pref;
    __shared__ int s_rank;
    int j = jobBase + blockIdx.x;
    const int* jb = &g_seljobs[j*6];
    const float* src = selSrc(jb[1], jb[2]);
    if(jb[0]==0){
        float med = blockRadixSelect(src, 0.f, 0, jb[3], shist, &s_pref, &s_rank);
        if(threadIdx.x==0) g_sv[jb[4]] = med;
        float mad = blockRadixSelect(src, med, 1, jb[3], shist, &s_pref, &s_rank);
        if(threadIdx.x==0) g_sv[jb[5]] = mad;
    } else {
        float v0 = blockRadixSelect(src, 0.f, 0, jb[3],   shist, &s_pref, &s_rank);
        if(threadIdx.x==0) g_sv[jb[4]] = v0;
        float v1 = blockRadixSelect(src, 0.f, 0, jb[3]+1, shist, &s_pref, &s_rank);
        if(threadIdx.x==0) g_sv[jb[5]] = v1;
    }
}

// ======================= pipeline kernels =======================
__global__ void kSobel(const float* lab){
    int idx = blockIdx.x*blockDim.x + threadIdx.x;
    if(idx >= BN) return;
    int b = idx / NPIX, p = idx % NPIX;
    int y = p / WW, x = p % WW;
    const float* L = lab + (size_t)b*3*NPIX;
    #define AT(yy,xx) (((yy)>=0&&(yy)<HH&&(xx)>=0&&(xx)<WW)?L[(yy)*WW+(xx)]:0.f)
    float l00=AT(y-1,x-1), l01=AT(y-1,x), l02=AT(y-1,x+1);
    float l10=AT(y,x-1),                  l12=AT(y,x+1);
    float l20=AT(y+1,x-1), l21=AT(y+1,x), l22=AT(y+1,x+1);
    #undef AT
    float gx = -l00 + l02 - 2.f*l10 + 2.f*l12 - l20 + l22;
    float gy = -l00 - 2.f*l01 - l02 + l20 + 2.f*l21 + l22;
    g_P[idx] = gx*gx + gy*gy;
    float av = L[NPIX + p], bv = L[2*NPIX + p];
    g_S[idx] = sqrtf(av*av + bv*bv + 1e-8f);
}

// E = avg3(P), fused with regression XtX/XtY accumulation
__global__ void kE(const float* lab){
    int idx = blockIdx.x*blockDim.x + threadIdx.x;   // grid exactly covers BN
    int b = idx / NPIX, p = idx % NPIX;
    int y = p / WW, x = p % WW;
    float s = 0.f;
    for(int dy=-1;dy<=1;dy++){ int yy=y+dy; if(yy<0||yy>=HH) continue;
      for(int dx=-1;dx<=1;dx++){ int xx=x+dx; if(xx<0||xx>=WW) continue;
        s += g_P[b*NPIX + yy*WW + xx]; } }
    float E = s / 9.f;
    g_E[idx] = E;
    double e = E, sv = g_S[idx], l = lab[(size_t)b*3*NPIX+p];
    double r;
    r=blockReduceD(e*e);  if(threadIdx.x==0) atomicAdd(&g_reg[b][0],r);
    r=blockReduceD(e*sv); if(threadIdx.x==0) atomicAdd(&g_reg[b][1],r);
    r=blockReduceD(sv*sv);if(threadIdx.x==0) atomicAdd(&g_reg[b][2],r);
    r=blockReduceD(e*l);  if(threadIdx.x==0) atomicAdd(&g_reg[b][3],r);
    r=blockReduceD(sv*l); if(threadIdx.x==0) atomicAdd(&g_reg[b][4],r);
}

__global__ void kSolve(){
    int b = threadIdx.x; if(b>=BB) return;
    double ee=g_reg[b][0]+1e-6, es=g_reg[b][1], ss=g_reg[b][2]+1e-6;
    double el=g_reg[b][3], sl=g_reg[b][4];
    double det = ee*ss - es*es;
    g_beta[b][0] = (ss*el - es*sl)/det;
    g_beta[b][1] = (ee*sl - es*el)/det;
    for(int i=0;i<5;i++) g_reg[b][i]=0.0;
}

// L_perp + fused global min/max (used later by GLD binning)
__global__ void kLperp(const float* lab, float* out){
    int idx = blockIdx.x*blockDim.x + threadIdx.x;
    int b = idx / NPIX, p = idx % NPIX;
    float v = lab[(size_t)b*3*NPIX+p] - (float)g_beta[b][0]*g_E[idx] - (float)g_beta[b][1]*g_S[idx];
    g_Lp[idx] = v;
    out[idx] = v;   // output #1
    unsigned k = f2u(v);
    __shared__ unsigned smn[256], smx[256];
    smn[threadIdx.x]=k; smx[threadIdx.x]=k;
    __syncthreads();
    for(int o=128;o>0;o>>=1){
        if(threadIdx.x<o){ smn[threadIdx.x]=min(smn[threadIdx.x],smn[threadIdx.x+o]);
                           smx[threadIdx.x]=max(smx[threadIdx.x],smx[threadIdx.x+o]); }
        __syncthreads();
    }
    if(threadIdx.x==0){ atomicMin(&g_mm[b][0],smn[0]); atomicMax(&g_mm[b][1],smx[0]); }
}

__global__ void kCovAcc(){
    int b = blockIdx.y;
    float md[3], sd[3];
    for(int f=0;f<3;f++){ md[f]=g_sv[b*3+f]; sd[f]=g_sv[6+b*3+f]*1.4826f+1e-8f; }
    double a[9]={0,0,0,0,0,0,0,0,0};
    int per = (NPIX + gridDim.x - 1)/gridDim.x;
    int lo = blockIdx.x*per, hi = min(lo+per, NPIX);
    for(int p=lo+threadIdx.x;p<hi;p+=blockDim.x){
        float z0=(g_Lp[b*NPIX+p]-md[0])/sd[0];
        float z1=(g_E [b*NPIX+p]-md[1])/sd[1];
        float z2=(g_S [b*NPIX+p]-md[2])/sd[2];
        a[0]+=z0; a[1]+=z1; a[2]+=z2;
        a[3]+=(double)z0*z0; a[4]+=(double)z0*z1; a[5]+=(double)z0*z2;
        a[6]+=(double)z1*z1; a[7]+=(double)z1*z2; a[8]+=(double)z2*z2;
    }
    for(int m=0;m<9;m++){ double r=blockReduceD(a[m]); if(threadIdx.x==0) atomicAdd(&g_cacc[b][m],r); }
}

// eigh of clamped 3x3 cov -> whitening; ALSO ES 2x2 inverse from same sums
__global__ void kEigh(){
    int b = threadIdx.x; if(b>=BB) return;
    double N = (double)NPIX;
    double mu[3]; for(int i=0;i<3;i++){ mu[i]=g_cacc[b][i]/N; g_mean3[b][i]=mu[i]; }
    double C[9];
    C[0]=g_cacc[b][3]/N-mu[0]*mu[0]; C[1]=g_cacc[b][4]/N-mu[0]*mu[1]; C[2]=g_cacc[b][5]/N-mu[0]*mu[2];
    C[4]=g_cacc[b][6]/N-mu[1]*mu[1]; C[5]=g_cacc[b][7]/N-mu[1]*mu[2]; C[8]=g_cacc[b][8]/N-mu[2]*mu[2];
    C[3]=C[1]; C[6]=C[2]; C[7]=C[5];
    // ES 2x2 inverse (E,S are features 1,2 with same robust-z as X3f)
    {
        double mE=mu[1], mS=mu[2];
        double c00=C[4]+1e-6, c01=C[5], c11=C[8]+1e-6;
        double det=c00*c11-c01*c01;
        g_esinv[b][0]=c11/det; g_esinv[b][1]=-c01/det; g_esinv[b][2]=c00/det;
        g_esinv[b][3]=mE; g_esinv[b][4]=mS;
    }
    for(int i=0;i<9;i++) C[i] = C[i] > 1e-8 ? C[i] : 1e-8;   // elementwise max, matches reference
    double e[3], V[9];
    eigh3(C, e, V);
    for(int i=0;i<3;i++) for(int j=0;j<3;j++){
        double s=0; for(int k2=0;k2<3;k2++) s += V[i*3+k2]*(1.0/sqrt(e[k2]))*V[j*3+k2];
        g_wwh[b][i*3+j]=s;
    }
    for(int i=0;i<9;i++) g_cacc[b][i]=0.0;
}

__global__ void kCdir(const float* arand){
    int t = threadIdx.x; if(t>=BB*NDIR) return;
    int b = t / NDIR, d = t % NDIR;
    float a0=arand[(b*NDIR+d)*3+0], a1=arand[(b*NDIR+d)*3+1], a2=arand[(b*NDIR+d)*3+2];
    float nr = sqrtf(a0*a0+a1*a1+a2*a2) + 1e-12f;
    double an[3]={a0/nr,a1/nr,a2/nr};
    for(int j=0;j<3;j++){
        double s=0; for(int i=0;i<3;i++) s += g_wwh[b][j*3+i]*an[i];
        g_cdir[(b*NDIR+d)*3+j]=(float)s;
    }
}

__global__ void kKurtAcc(){
    int b = blockIdx.z, g8 = blockIdx.y*8;
    int lane = threadIdx.x & 31;
    float md[3], sd[3], mn[3];
    for(int f=0;f<3;f++){ md[f]=g_sv[b*3+f]; sd[f]=g_sv[6+b*3+f]*1.4826f+1e-8f; mn[f]=(float)g_mean3[b][f]; }
    float c[8][3];
    for(int d=0;d<8;d++) for(int j=0;j<3;j++) c[d][j]=g_cdir[(b*NDIR+g8+d)*3+j];
    float acc[32];
    for(int i=0;i<32;i++) acc[i]=0.f;
    int per = (NPIX + gridDim.x - 1)/gridDim.x;
    int lo = blockIdx.x*per, hi = min(lo+per, NPIX);
    for(int p=lo+threadIdx.x;p<hi;p+=blockDim.x){
        float d0=(g_Lp[b*NPIX+p]-md[0])/sd[0]-mn[0];
        float d1=(g_E [b*NPIX+p]-md[1])/sd[1]-mn[1];
        float d2=(g_S [b*NPIX+p]-md[2])/sd[2]-mn[2];
        #pragma unroll
        for(int d=0;d<8;d++){
            float z = d0*c[d][0]+d1*c[d][1]+d2*c[d][2];
            float z2=z*z;
            acc[d*4+0]+=z; acc[d*4+1]+=z2; acc[d*4+2]+=z2*z; acc[d*4+3]+=z2*z2;
        }
    }
    __shared__ float sacc[32];
    if(threadIdx.x<32) sacc[threadIdx.x]=0.f;
    __syncthreads();
    #pragma unroll
    for(int v=0; v<32; v++){
        float x = acc[v];
        for(int o=16;o;o>>=1) x += __shfl_down_sync(0xffffffffu,x,o);
        if(lane==0) atomicAdd(&sacc[v], x);
    }
    __syncthreads();
    if(threadIdx.x<32) atomicAdd(&g_dirm[b][g8+threadIdx.x/4][threadIdx.x%4],(double)sacc[threadIdx.x]);
}

__global__ void kKurtPick(){
    int b = threadIdx.x; if(b>=BB) return;
    double N=(double)NPIX, bestv=-1.0; int best=0;
    for(int d=0;d<NDIR;d++){
        double m1=g_dirm[b][d][0]/N, s2=g_dirm[b][d][1]/N, s3=g_dirm[b][d][2]/N, s4=g_dirm[b][d][3]/N;
        double m2=(s2-m1*m1)+1e-12;
        double m4=s4-4.0*m1*s3+6.0*m1*m1*s2-3.0*m1*m1*m1*m1;
        double kurt=fabs(m4/(m2*m2)-3.0);
        if(kurt>bestv){bestv=kurt;best=d;}
    }
    for(int j=0;j<3;j++) g_cbest[b][j]=g_cdir[(b*NDIR+best)*3+j];
    for(int d=0;d<NDIR;d++) for(int m=0;m<4;m++) g_dirm[b][d][m]=0.0;
}

__global__ void kZb(){
    int idx = blockIdx.x*blockDim.x + threadIdx.x;
    if(idx >= BN) return;
    int b = idx / NPIX;
    float md0=g_sv[b*3+0], md1=g_sv[b*3+1], md2=g_sv[b*3+2];
    float sd0=g_sv[6+b*3+0]*1.4826f+1e-8f, sd1=g_sv[6+b*3+1]*1.4826f+1e-8f, sd2=g_sv[6+b*3+2]*1.4826f+1e-8f;
    float d0=(g_Lp[idx]-md0)/sd0-(float)g_mean3[b][0];
    float d1=(g_E [idx]-md1)/sd1-(float)g_mean3[b][1];
    float d2=(g_S [idx]-md2)/sd2-(float)g_mean3[b][2];
    g_zb[idx] = d0*g_cbest[b][0]+d1*g_cbest[b][1]+d2*g_cbest[b][2];
}

// ================= fused EM: init + 9 iterations + final E-step -> Ra =================
__global__ void kEM(){
    int b = blockIdx.x;
    __shared__ double par[6];   // mu0 mu1 var0 var1 pi0 pi1
    __shared__ double red[6];
    if(threadIdx.x==0){
        float q25 = g_sv[12+4*b] + 0.75f*(g_sv[13+4*b]-g_sv[12+4*b]);
        float q75 = g_sv[14+4*b] + 0.25f*(g_sv[15+4*b]-g_sv[14+4*b]);
        par[0]=q25; par[1]=q75; par[2]=1.0; par[3]=1.0; par[4]=0.5; par[5]=0.5;
    }
    __syncthreads();
    const float* zb = g_zb + b*NPIX;
    for(int it=0; it<9; it++){
        float mu0=(float)par[0], mu1=(float)par[1];
        float v0=(float)par[2]+1e-6f, v1=(float)par[3]+1e-6f;
        float lw0=-0.5f*logf(v0)+logf((float)par[4]+1e-8f);
        float lw1=-0.5f*logf(v1)+logf((float)par[5]+1e-8f);
        float a0=0,a1=0,a2=0,a3=0,a4=0,a5=0;
        for(int p=threadIdx.x;p<NPIX;p+=blockDim.x){
            float x=zb[p];
            float lp0=-0.5f*(x-mu0)*(x-mu0)/v0+lw0;
            float lp1=-0.5f*(x-mu1)*(x-mu1)/v1+lw1;
            float R0=1.f/(1.f+expf(lp1-lp0));
            float R1=1.f/(1.f+expf(lp0-lp1));
            a0+=R0; a1+=R0*x; a2+=R0*x*x;
            a3+=R1; a4+=R1*x; a5+=R1*x*x;
        }
        double s[6]={a0,a1,a2,a3,a4,a5};
        for(int m=0;m<6;m++){
            double r=blockReduceD(s[m]);
            if(threadIdx.x==0) red[m]=r;
        }
        __syncthreads();
        if(threadIdx.x==0){
            for(int k=0;k<2;k++){
                double Sr=red[k*3], Sx=red[k*3+1], Sxx=red[k*3+2];
                double den=Sr+1e-8, mu=Sx/den;
                double var=(Sxx-2.0*mu*Sx+mu*mu*Sr)/den+1e-6;
                par[k]=mu; par[2+k]=var; par[4+k]=Sr/(double)NPIX;
            }
        }
        __syncthreads();
    }
    float mu0=(float)par[0], mu1=(float)par[1];
    float v0=(float)par[2]+1e-6f, v1=(float)par[3]+1e-6f;
    float lw0=-0.5f*logf(v0)+logf((float)par[4]+1e-8f);
    float lw1=-0.5f*logf(v1)+logf((float)par[5]+1e-8f);
    for(int p=threadIdx.x;p<NPIX;p+=blockDim.x){
        float x=zb[p];
        float lp0=-0.5f*(x-mu0)*(x-mu0)/v0+lw0;
        float lp1=-0.5f*(x-mu1)*(x-mu1)/v1+lw1;
        float R0=1.f/(1.f+expf(lp1-lp0));
        float R1=1.f/(1.f+expf(lp0-lp1));
        float r0=powf(R0,0.9f), r1=powf(R1,0.9f);
        float ssum=r0+r1+1e-8f;
        g_Ra[(b*2+0)*NPIX+p]=r0/ssum;
        g_Ra[(b*2+1)*NPIX+p]=r1/ssum;
    }
}

__global__ void kClusterAcc(){
    int bk = blockIdx.y; int b=bk>>1, k=bk&1;
    double a[10]={0,0,0,0,0,0,0,0,0,0};
    int per = (NPIX + gridDim.x - 1)/gridDim.x;
    int lo = blockIdx.x*per, hi = min(lo+per, NPIX);
    for(int p=lo+threadIdx.x;p<hi;p+=blockDim.x){
        double w=g_Ra[bk*NPIX+p];
        double x0=g_Lp[b*NPIX+p], x1=g_E[b*NPIX+p], x2=g_S[b*NPIX+p];
        a[0]+=w; a[1]+=w*x0; a[2]+=w*x1; a[3]+=w*x2;
        a[4]+=w*x0*x0; a[5]+=w*x0*x1; a[6]+=w*x0*x2;
        a[7]+=w*x1*x1; a[8]+=w*x1*x2; a[9]+=w*x2*x2;
    }
    for(int m=0;m<10;m++){ double r=blockReduceD(a[m]); if(threadIdx.x==0) atomicAdd(&g_clacc[b][k][m],r); }
}

__global__ void kClusterInv(){
    int t = threadIdx.x; if(t>=4) return;
    int b=t>>1, k=t&1;
    double* A = g_clacc[b][k];
    double Ws = A[0] + 1e-8;
    double mu[3] = {A[1]/Ws, A[2]/Ws, A[3]/Ws};
    double Sx[3] = {A[1], A[2], A[3]};
    double Sxx[9] = {A[4],A[5],A[6], A[5],A[7],A[8], A[6],A[8],A[9]};
    double C[9];
    for(int i=0;i<3;i++) for(int j=0;j<3;j++)
        C[i*3+j] = (Sxx[i*3+j] - mu[i]*Sx[j] - mu[j]*Sx[i] + A[0]*mu[i]*mu[j])/Ws + ((i==j)?1e-6:0.0);
    double I[9]; inv3(C, I);
    for(int i=0;i<9;i++) g_clinv[b][k][i]=I[i];
    for(int i=0;i<3;i++) g_clmu[b][k][i]=mu[i];
    for(int i=0;i<10;i++) A[i]=0.0;
}

__global__ void kDM(){
    int idx = blockIdx.x*blockDim.x + threadIdx.x;
    if(idx >= BN) return;
    int b = idx / NPIX, p = idx % NPIX;
    float X[3] = {g_Lp[idx], g_E[idx], g_S[idx]};
    float ra0=g_Ra[(b*2+0)*NPIX+p], ra1=g_Ra[(b*2+1)*NPIX+p];
    float ssum = ra0+ra1+2e-8f;
    float DM=0.f;
    for(int k=0;k<2;k++){
        float xm0=X[0]-(float)g_clmu[b][k][0];
        float xm1=X[1]-(float)g_clmu[b][k][1];
        float xm2=X[2]-(float)g_clmu[b][k][2];
        const double* I=g_clinv[b][k];
        float q = xm0*xm0*(float)I[0] + xm1*xm1*(float)I[4] + xm2*xm2*(float)I[8]
                + 2.f*xm0*xm1*(float)I[1] + 2.f*xm0*xm2*(float)I[2] + 2.f*xm1*xm2*(float)I[5];
        float Dk = sqrtf(q + 1e-8f);
        float Rt = ((k==0?ra0:ra1)+1e-8f)/ssum;
        DM += Rt*Dk;
    }
    g_DM[idx]=DM;
}

__global__ void kBoxH(){
    int bk = blockIdx.y; int b=bk>>1;
    int p = blockIdx.x*blockDim.x + threadIdx.x;
    if(p >= NPIX) return;
    int y = p / WW, x = p % WW;
    float s0=0.f,s1=0.f,s2=0.f;
    int lo = max(x-7,0), hi = min(x+7,WW-1);
    for(int xx=lo;xx<=hi;xx++){
        float r = g_Ra[bk*NPIX + y*WW + xx];
        float l = g_Lp[b*NPIX + y*WW + xx];
        s0+=r; s1+=r*l; s2+=r*l*l;
    }
    g_t0[bk*NPIX+p]=s0; g_t1[bk*NPIX+p]=s1; g_t2[bk*NPIX+p]=s2;
}

__global__ void kBoxV(){
    int bk = blockIdx.y; int b=bk>>1;
    int p = blockIdx.x*blockDim.x + threadIdx.x;
    if(p >= NPIX) return;
    int y = p / WW, x = p % WW;
    float s0=0.f,s1=0.f,s2=0.f;
    int lo = max(y-7,0), hi = min(y+7,HH-1);
    for(int yy=lo;yy<=hi;yy++){
        s0+=g_t0[bk*NPIX+yy*WW+x]; s1+=g_t1[bk*NPIX+yy*WW+x]; s2+=g_t2[bk*NPIX+yy*WW+x];
    }
    float cy = (float)(min(y+8,HH)-max(y-7,0));
    float cx = (float)(min(x+8,WW)-max(x-7,0));
    float c = cy*cx;
    float a0=s0/c, a1=s1/c, a2=s2/c;
    float den = a0 + 1e-8f;
    float mu = a1/den;
    float vb = fmaxf(a2/den - mu*mu, 1e-8f);
    g_lla[bk*NPIX+p] = fabsf(g_Lp[b*NPIX+p]-mu)/(sqrtf(vb)+1e-8f);
    g_den[bk*NPIX+p] = a0;
}

// bin index + fused global weighted histogram (both k planes)
__global__ void kBinIdxGhist(){
    __shared__ float sh[64];
    if(threadIdx.x<64) sh[threadIdx.x]=0.f;
    __syncthreads();
    int idx = blockIdx.x*blockDim.x + threadIdx.x;
    int b = idx / NPIX, p = idx % NPIX;
    float mn = u2f(g_mm[b][0]), mx = u2f(g_mm[b][1]);
    float ln = (g_Lp[idx]-mn)/(mx-mn+1e-8f);
    ln = fminf(fmaxf(ln,0.f),1.f);
    int c = (int)(ln*32.f); c = c<0?0:(c>31?31:c);
    g_idxb[idx] = (unsigned char)c;
    atomicAdd(&sh[c],    g_Ra[(b*2+0)*NPIX+p]);
    atomicAdd(&sh[32+c], g_Ra[(b*2+1)*NPIX+p]);
    __syncthreads();
    if(threadIdx.x<64 && sh[threadIdx.x]!=0.f)
        atomicAdd(&g_ghist[b][threadIdx.x>>5][threadIdx.x&31],(double)sh[threadIdx.x]);
}

__global__ void kGcdf(){
    int t = threadIdx.x; if(t>=4) return;
    int b=t>>1, k=t&1;
    double tot=0; for(int c=0;c<32;c++) tot += g_ghist[b][k][c];
    double cum=0;
    for(int c=0;c<32;c++){ cum += g_ghist[b][k][c]/(tot+1e-8); g_gcdf[b][k][c]=(float)cum; g_ghist[b][k][c]=0.0; }
    if(k==0){ g_mm[b][0]=0xFFFFFFFFu; g_mm[b][1]=0u; }
}

// vertical sliding per-column histogram, maintained directly in BIN-PREFIX form,
// segmented along y (8 segments of 48 rows, 14-row warm-up)
__global__ void kColHist(){
    int bk = blockIdx.z; int b=bk>>1;
    int warp = threadIdx.x>>5, lane = threadIdx.x&31;
    int x = blockIdx.x*4 + warp;
    int y0 = blockIdx.y*SEG;
    const float* rk = g_Ra + bk*NPIX;
    const unsigned char* bi = g_idxb + b*NPIX;
    float P = 0.f;
    for(int r=y0-7; r<=y0+6; r++){
        if(r>=0){ float v=rk[r*WW+x]; int bn=bi[r*WW+x]; if(lane>=bn) P+=v; }
    }
    for(int y=y0; y<y0+SEG; y++){
        int ra=y+7;
        if(ra<HH){ float v=rk[ra*WW+x]; int bn=bi[ra*WW+x]; if(lane>=bn) P+=v; }
        g_colsum[((size_t)(bk*HH+y)*WW + x)*32 + lane] = P;
        int rr=y-7;
        if(rr>=0){ float v=rk[rr*WW+x]; int bn=bi[rr*WW+x]; if(lane>=bn) P-=v; }
    }
}

// horizontal sliding sum of prefix-columns -> loc CDF directly; segmented along x
__global__ void kGLD(){
    int bk = blockIdx.z; int b=bk>>1, k=bk&1;
    int warp = threadIdx.x>>5, lane = threadIdx.x&31;
    int y = blockIdx.x*4 + warp;
    int x0 = blockIdx.y*SEG;
    const float* cs = g_colsum + (size_t)(bk*HH+y)*WW*32;
    float gc = g_gcdf[b][k][lane];
    float S = 0.f;
    for(int xx=x0-7; xx<=x0+6; xx++) if(xx>=0) S += cs[xx*32+lane];
    float cy = (float)(min(y+8,HH)-max(y-7,0));
    for(int x=x0; x<x0+SEG; x++){
        if(x+7<WW) S += cs[(x+7)*32+lane];
        float cx = (float)(min(x+8,WW)-max(x-7,0));
        float den = g_den[bk*NPIX + y*WW+x] + 1e-8f;
        float diff = fabsf(S/(cy*cx)/den - gc);
        for(int o=16;o;o>>=1) diff += __shfl_down_sync(0xffffffffu,diff,o);
        if(lane==0) g_gld[bk*NPIX + y*WW+x] = diff*(1.f/32.f);
        if(x-7>=0) S -= cs[(x-7)*32+lane];
    }
}

__global__ void kGamma(){
    int idx = blockIdx.x*blockDim.x + threadIdx.x;
    if(idx >= BN) return;
    int b = idx / NPIX, p = idx % NPIX;
    float gamma = 1.f;
    for(int k=0;k<2;k++){
        int s = b*2+k;
        float zl = (g_lla[s*NPIX+p]-g_sv[20+s])/(g_sv[24+s]*1.4826f+1e-8f);
        float zg = (g_gld[s*NPIX+p]-g_sv[28+s])/(g_sv[32+s]*1.4826f+1e-8f);
        gamma += g_Ra[s*NPIX+p]*(0.5f*softplusf(zl)+0.5f*softplusf(zg));
    }
    float mdE=g_sv[b*3+1], mdS=g_sv[b*3+2];
    float sdE=g_sv[6+b*3+1]*1.4826f+1e-8f, sdS=g_sv[6+b*3+2]*1.4826f+1e-8f;
    float dE=(g_E[idx]-mdE)/sdE-(float)g_esinv[b][3];
    float dS=(g_S[idx]-mdS)/sdS-(float)g_esinv[b][4];
    float d2 = dE*dE*(float)g_esinv[b][0] + 2.f*dE*dS*(float)g_esinv[b][1] + dS*dS*(float)g_esinv[b][2];
    float Rs = expf(-0.5f*d2);
    g_La[idx] = fmaxf(g_DM[idx]*gamma*(1.f-Rs), 0.f);
}

__global__ void kFinal(float* out){
    int idx = blockIdx.x*blockDim.x + threadIdx.x;
    if(idx >= BN) return;
    int b = idx / NPIX;
    float q1 = g_sv[36+4*b] + 0.55f*(g_sv[37+4*b]-g_sv[36+4*b]);
    float q9 = g_sv[38+4*b] + 0.45f*(g_sv[39+4*b]-g_sv[38+4*b]);
    float v = (g_La[idx]-q1)/(q9-q1+1e-8f);
    out[BN + idx] = fminf(fmaxf(v,0.f),1.f);   // output #2
}

// ======================= host =======================
extern "C" void kernel_launch(void* const* d_in, const int* in_sizes, int n_in,
                              void* d_out, int out_size){
    const float* lab   = (const float*)d_in[0];
    const float* arand = (const float*)d_in[1];
    float* out = (float*)d_out;
    const int EB = (BN+255)/256;      // 1152 (exact)

    kSobel<<<EB,256>>>(lab);
    kE<<<EB,256>>>(lab);
    kSolve<<<1,32>>>();
    kLperp<<<EB,256>>>(lab,out);

    selFused<<<6,1024>>>(0);          // med+MAD of Lp,E,S (both batches)

    kCovAcc<<<dim3(32,BB),256>>>();
    kEigh<<<1,32>>>();
    kCdir<<<1,256>>>(arand);
    kKurtAcc<<<dim3(32,16,BB),256>>>();
    kKurtPick<<<1,32>>>();
    kZb<<<EB,256>>>();

    selFused<<<4,1024>>>(6);          // z_best quartile brackets
    kEM<<<BB,1024>>>();               // init + 9 EM iters + final R^alpha -> Ra

    kClusterAcc<<<dim3(32,4),256>>>();
    kClusterInv<<<1,32>>>();
    kDM<<<EB,256>>>();

    kBoxH<<<dim3(576,4),256>>>();
    kBoxV<<<dim3(576,4),256>>>();
    selFused<<<4,1024>>>(10);         // LLA med+MAD

    kBinIdxGhist<<<EB,256>>>();
    kGcdf<<<1,32>>>();
    kColHist<<<dim3(96,8,4),128>>>();
    kGLD<<<dim3(96,8,4),128>>>();
    selFused<<<4,1024>>>(14);         // GLD med+MAD

    kGamma<<<EB,256>>>();
    selFused<<<4,1024>>>(18);         // L_anom 1%/99% brackets
    kFinal<<<EB,256>>>(out);
}

// round 6
// speedup vs baseline: 1.4664x; 1.4664x over previous
#include <cuda_runtime.h>
#include <math.h>

#define HH 384
#define WW 384
#define NPIX (HH*WW)          // 147456
#define BB 2
#define BN (BB*NPIX)          // 294912
#define NDIR 128
#define SEG 48
#define EMB 32                // kEM total blocks (16 per batch)

// ======================= scratch buffers =======================
__device__ float g_P[BN];
__device__ float g_E[BN];
__device__ float g_S[BN];
__device__ float g_Lp[BN];
__device__ float g_zb[BN];
__device__ float g_Ra[2*BN];     // [(b*2+k)*NPIX+n]
__device__ float g_DM[BN];
__device__ float g_t0[2*BN], g_t1[2*BN], g_t2[2*BN];
__device__ float g_lla[2*BN];
__device__ float g_den[2*BN];
__device__ float g_gld[2*BN];
__device__ float g_La[BN];
__device__ unsigned char g_idxb[BN];
__device__ float g_colsum[(size_t)4*NPIX*32];   // [bk][y][x][bin] (bin-prefix form)

// ======================= small state =======================
__device__ float    g_sv[64];
__device__ unsigned g_mm[BB][2] = {{0xFFFFFFFFu,0u},{0xFFFFFFFFu,0u}};
__device__ double   g_reg[BB][5];
__device__ double   g_beta[BB][2];
__device__ double   g_cacc[BB][9];
__device__ double   g_mean3[BB][3];
__device__ double   g_wwh[BB][9];
__device__ float    g_cdir[BB*NDIR*3];
__device__ float    g_cbest[BB][3];
__device__ double   g_dirm[BB][NDIR][4];
__device__ double   g_emacc[BB][6];
__device__ double   g_empar[BB][6];   // mu0 mu1 var0 var1 pi0 pi1
__device__ double   g_clacc[BB][2][10];
__device__ double   g_clmu[BB][2][3];
__device__ double   g_clinv[BB][2][9];
__device__ double   g_ghist[BB][2][32];
__device__ float    g_gcdf[BB][2][32];
__device__ double   g_esinv[BB][6];   // i00 i01 i11 meanE meanS

// grid-wide barrier state (monotonic generation; arrive self-resets)
__device__ int g_barArrive = 0;
__device__ int g_barGen = 0;

static __device__ __forceinline__ void gridBarrier(int nb){
    __syncthreads();
    if(threadIdx.x==0){
        __threadfence();
        int gen = *(volatile int*)&g_barGen;
        if(atomicAdd(&g_barArrive,1)==nb-1){
            g_barArrive = 0;
            __threadfence();
            *(volatile int*)&g_barGen = gen+1;
        } else {
            while(*(volatile int*)&g_barGen == gen) { }
        }
    }
    __syncthreads();
}

static __device__ __forceinline__ double vloadd(const double* p){ return *(volatile const double*)p; }
static __device__ __forceinline__ void vstored(double* p, double v){ *(volatile double*)p = v; }

// ======================= helpers =======================
static __device__ __forceinline__ unsigned f2u(float f){
    unsigned u = __float_as_uint(f);
    return (u & 0x80000000u) ? ~u : (u | 0x80000000u);
}
static __device__ __forceinline__ float u2f(unsigned u){
    unsigned v = (u & 0x80000000u) ? (u & 0x7FFFFFFFu) : ~u;
    return __uint_as_float(v);
}
static __device__ __forceinline__ float softplusf(float x){
    float t = log1pf(expf(-fabsf(x)));
    return x >= 0.f ? x + t : t;
}
static __device__ double blockReduceD(double v){
    __shared__ double sh[32];
    int lane = threadIdx.x & 31, wid = threadIdx.x >> 5;
    for (int o=16;o;o>>=1) v += __shfl_down_sync(0xffffffffu, v, o);
    if (lane==0) sh[wid] = v;
    __syncthreads();
    int nw = (blockDim.x + 31) >> 5;
    v = (threadIdx.x < nw) ? sh[threadIdx.x] : 0.0;
    if (wid==0) for (int o=16;o;o>>=1) v += __shfl_down_sync(0xffffffffu, v, o);
    __syncthreads();
    return v;
}
static __device__ void eigh3(const double* A, double* e, double* V){
    double a[9]; for(int i=0;i<9;i++) a[i]=A[i];
    for(int i=0;i<9;i++) V[i] = (i%4==0)?1.0:0.0;
    for(int sweep=0;sweep<40;sweep++){
        double off = fabs(a[1])+fabs(a[2])+fabs(a[5]);
        if(off < 1e-300) break;
        for(int p=0;p<2;p++) for(int q=p+1;q<3;q++){
            double apq=a[p*3+q];
            if(fabs(apq) < 1e-300) continue;
            double app=a[p*3+p], aqq=a[q*3+q];
            double th=(aqq-app)/(2.0*apq);
            double t=(th>=0?1.0:-1.0)/(fabs(th)+sqrt(th*th+1.0));
            double c=1.0/sqrt(t*t+1.0), s=t*c;
            for(int i=0;i<3;i++){ double x=a[i*3+p],y=a[i*3+q]; a[i*3+p]=c*x-s*y; a[i*3+q]=s*x+c*y; }
            for(int i=0;i<3;i++){ double x=a[p*3+i],y=a[q*3+i]; a[p*3+i]=c*x-s*y; a[q*3+i]=s*x+c*y; }
            for(int i=0;i<3;i++){ double x=V[i*3+p],y=V[i*3+q]; V[i*3+p]=c*x-s*y; V[i*3+q]=s*x+c*y; }
        }
    }
    e[0]=a[0]; e[1]=a[4]; e[2]=a[8];
}
static __device__ void inv3(const double* m, double* inv){
    double a=m[0],b=m[1],c=m[2],d=m[3],e=m[4],f=m[5],g=m[6],h=m[7],i=m[8];
    double A=e*i-f*h, B=c*h-b*i, C=b*f-c*e;
    double D=f*g-d*i, E=a*i-c*g, F=c*d-a*f;
    double G=d*h-e*g, Hh=b*g-a*h, I=a*e-b*d;
    double det=a*A+b*D+c*G, id=1.0/det;
    inv[0]=A*id; inv[1]=B*id; inv[2]=C*id;
    inv[3]=D*id; inv[4]=E*id; inv[5]=F*id;
    inv[6]=G*id; inv[7]=Hh*id; inv[8]=I*id;
}

// ======================= fused radix select (3 passes: 11/11/10 bits) =======================
// jobs: {kind, type, b, rank, slotA, slotB}
// kind 0 = median (rank) -> slotA, then MAD -> slotB
// kind 1 = value at rank -> slotA, value at rank+1 -> slotB
__device__ const int g_seljobs[22*6] = {
 // phase A (base 0): med+MAD of Lp,E,S per batch
 0,0,0,73727,0,6,   0,1,0,73727,1,7,   0,2,0,73727,2,8,
 0,0,1,73727,3,9,   0,1,1,73727,4,10,  0,2,1,73727,5,11,
 // phase Z (base 6): zb quartile brackets
 1,3,0,36863,12,13,  1,3,0,110591,14,15,  1,3,1,36863,16,17,  1,3,1,110591,18,19,
 // phase L (base 10): LLA med+MAD
 0,4,0,73727,20,24,  0,5,0,73727,21,25,  0,4,1,73727,22,26,  0,5,1,73727,23,27,
 // phase G (base 14): GLD med+MAD
 0,6,0,73727,28,32,  0,7,0,73727,29,33,  0,6,1,73727,30,34,  0,7,1,73727,31,35,
 // phase F (base 18): La 1%/99% brackets
 1,8,0,1474,36,37,  1,8,0,145980,38,39,  1,8,1,1474,40,41,  1,8,1,145980,42,43
};

static __device__ const float* selSrc(int type, int b){
    switch(type){
        case 0: return g_Lp + b*NPIX;
        case 1: return g_E  + b*NPIX;
        case 2: return g_S  + b*NPIX;
        case 3: return g_zb + b*NPIX;
        case 4: return g_lla + (b*2+0)*NPIX;
        case 5: return g_lla + (b*2+1)*NPIX;
        case 6: return g_gld + (b*2+0)*NPIX;
        case 7: return g_gld + (b*2+1)*NPIX;
        default: return g_La + b*NPIX;
    }
}

static __device__ float radixSel3(const float4* __restrict__ src4, float ref, int useAbs, int rank,
                                  unsigned* shist, unsigned* st){
    // st[0] = pref, st[1] = remaining rank
    if(threadIdx.x==0){ st[0]=0u; st[1]=(unsigned)rank; }
    for(int pass=0; pass<3; pass++){
        int nb = (pass==2)?1024:2048;
        __syncthreads();
        for(int i=threadIdx.x;i<nb;i+=blockDim.x) shist[i]=0u;
        __syncthreads();
        unsigned pref = st[0];
        for(int i=threadIdx.x;i<NPIX/4;i+=blockDim.x){
            float4 v4 = src4[i];
            float vv[4] = {v4.x, v4.y, v4.z, v4.w};
            #pragma unroll
            for(int c=0;c<4;c++){
                float v = vv[c]; if(useAbs) v = fabsf(v - ref);
                unsigned key = f2u(v);
                if(pass==0){
                    atomicAdd(&shist[key>>21],1u);
                } else if(pass==1){
                    if((key>>21)==(pref>>21)) atomicAdd(&shist[(key>>10)&2047u],1u);
                } else {
                    if((key>>10)==(pref>>10)) atomicAdd(&shist[key&1023u],1u);
                }
            }
        }
        __syncthreads();
        if(threadIdx.x < 32){
            int lane = threadIdx.x, per = nb>>5;
            unsigned s=0u;
            for(int i=0;i<per;i++) s += shist[lane*per+i];
            unsigned cum=s;
            #pragma unroll
            for(int o=1;o<32;o<<=1){ unsigned t=__shfl_up_sync(0xffffffffu,cum,o); if(lane>=o) cum+=t; }
            unsigned prev=cum-s;
            unsigned rk = st[1];
            __syncwarp();
            if(prev<=rk && rk<cum){
                unsigned rr = rk - prev; int bin = lane*per;
                for(int i=0;i<per;i++){ unsigned c=shist[lane*per+i]; if(rr<c){ bin=lane*per+i; break;} rr-=c; }
                st[1]=rr;
                if(pass==0)      st[0] = ((unsigned)bin)<<21;
                else if(pass==1) st[0] = pref | (((unsigned)bin)<<10);
                else             st[0] = pref | (unsigned)bin;
            }
        }
    }
    __syncthreads();
    return u2f(st[0]);
}

__global__ void selFused(int jobBase){
    __shared__ unsigned shist[2048];
    __shared__ unsigned st[2];
    int j = jobBase + blockIdx.x;
    const int* jb = &g_seljobs[j*6];
    const float4* src = (const float4*)selSrc(jb[1], jb[2]);
    if(jb[0]==0){
        float med = radixSel3(src, 0.f, 0, jb[3], shist, st);
        if(threadIdx.x==0) g_sv[jb[4]] = med;
        float mad = radixSel3(src, med, 1, jb[3], shist, st);
        if(threadIdx.x==0) g_sv[jb[5]] = mad;
    } else {
        float v0 = radixSel3(src, 0.f, 0, jb[3],   shist, st);
        if(threadIdx.x==0) g_sv[jb[4]] = v0;
        float v1 = radixSel3(src, 0.f, 0, jb[3]+1, shist, st);
        if(threadIdx.x==0) g_sv[jb[5]] = v1;
    }
}

// ======================= pipeline kernels =======================
__global__ void kSobel(const float* __restrict__ lab){
    int idx = blockIdx.x*blockDim.x + threadIdx.x;
    int b = idx / NPIX, p = idx % NPIX;
    int y = p / WW, x = p % WW;
    const float* L = lab + (size_t)b*3*NPIX;
    #define AT(yy,xx) (((yy)>=0&&(yy)<HH&&(xx)>=0&&(xx)<WW)?L[(yy)*WW+(xx)]:0.f)
    float l00=AT(y-1,x-1), l01=AT(y-1,x), l02=AT(y-1,x+1);
    float l10=AT(y,x-1),                  l12=AT(y,x+1);
    float l20=AT(y+1,x-1), l21=AT(y+1,x), l22=AT(y+1,x+1);
    #undef AT
    float gx = -l00 + l02 - 2.f*l10 + 2.f*l12 - l20 + l22;
    float gy = -l00 - 2.f*l01 - l02 + l20 + 2.f*l21 + l22;
    g_P[idx] = gx*gx + gy*gy;
    float av = L[NPIX + p], bv = L[2*NPIX + p];
    g_S[idx] = sqrtf(av*av + bv*bv + 1e-8f);
}

// E = avg3(P), fused with regression XtX/XtY accumulation
__global__ void kE(const float* __restrict__ lab){
    int idx = blockIdx.x*blockDim.x + threadIdx.x;
    int b = idx / NPIX, p = idx % NPIX;
    int y = p / WW, x = p % WW;
    float s = 0.f;
    for(int dy=-1;dy<=1;dy++){ int yy=y+dy; if(yy<0||yy>=HH) continue;
      for(int dx=-1;dx<=1;dx++){ int xx=x+dx; if(xx<0||xx>=WW) continue;
        s += g_P[b*NPIX + yy*WW + xx]; } }
    float E = s / 9.f;
    g_E[idx] = E;
    double e = E, sv = g_S[idx], l = lab[(size_t)b*3*NPIX+p];
    double r;
    r=blockReduceD(e*e);  if(threadIdx.x==0) atomicAdd(&g_reg[b][0],r);
    r=blockReduceD(e*sv); if(threadIdx.x==0) atomicAdd(&g_reg[b][1],r);
    r=blockReduceD(sv*sv);if(threadIdx.x==0) atomicAdd(&g_reg[b][2],r);
    r=blockReduceD(e*l);  if(threadIdx.x==0) atomicAdd(&g_reg[b][3],r);
    r=blockReduceD(sv*l); if(threadIdx.x==0) atomicAdd(&g_reg[b][4],r);
}

__global__ void kSolve(){
    int b = threadIdx.x; if(b>=BB) return;
    double ee=g_reg[b][0]+1e-6, es=g_reg[b][1], ss=g_reg[b][2]+1e-6;
    double el=g_reg[b][3], sl=g_reg[b][4];
    double det = ee*ss - es*es;
    g_beta[b][0] = (ss*el - es*sl)/det;
    g_beta[b][1] = (ee*sl - es*el)/det;
    for(int i=0;i<5;i++) g_reg[b][i]=0.0;
}

// L_perp + fused global min/max
__global__ void kLperp(const float* __restrict__ lab, float* __restrict__ out){
    int idx = blockIdx.x*blockDim.x + threadIdx.x;
    int b = idx / NPIX, p = idx % NPIX;
    float v = lab[(size_t)b*3*NPIX+p] - (float)g_beta[b][0]*g_E[idx] - (float)g_beta[b][1]*g_S[idx];
    g_Lp[idx] = v;
    out[idx] = v;   // output #1
    unsigned k = f2u(v);
    __shared__ unsigned smn[256], smx[256];
    smn[threadIdx.x]=k; smx[threadIdx.x]=k;
    __syncthreads();
    for(int o=128;o>0;o>>=1){
        if(threadIdx.x<o){ smn[threadIdx.x]=min(smn[threadIdx.x],smn[threadIdx.x+o]);
                           smx[threadIdx.x]=max(smx[threadIdx.x],smx[threadIdx.x+o]); }
        __syncthreads();
    }
    if(threadIdx.x==0){ atomicMin(&g_mm[b][0],smn[0]); atomicMax(&g_mm[b][1],smx[0]); }
}

// robust-z cov accumulation + eigh + whitening + ES inverse + direction whitening
// grid: 64 blocks x 256 (32 per batch); grid barrier, then block 0 finishes.
__global__ void kCovEighCdir(const float* __restrict__ arand){
    int b = blockIdx.x >> 5, chunk = blockIdx.x & 31;
    float md[3], sd[3];
    for(int f=0;f<3;f++){ md[f]=g_sv[b*3+f]; sd[f]=g_sv[6+b*3+f]*1.4826f+1e-8f; }
    double a[9]={0,0,0,0,0,0,0,0,0};
    int per = NPIX/32;
    int lo = chunk*per, hi = lo+per;
    for(int p=lo+threadIdx.x;p<hi;p+=blockDim.x){
        float z0=(g_Lp[b*NPIX+p]-md[0])/sd[0];
        float z1=(g_E [b*NPIX+p]-md[1])/sd[1];
        float z2=(g_S [b*NPIX+p]-md[2])/sd[2];
        a[0]+=z0; a[1]+=z1; a[2]+=z2;
        a[3]+=(double)z0*z0; a[4]+=(double)z0*z1; a[5]+=(double)z0*z2;
        a[6]+=(double)z1*z1; a[7]+=(double)z1*z2; a[8]+=(double)z2*z2;
    }
    for(int m=0;m<9;m++){ double r=blockReduceD(a[m]); if(threadIdx.x==0) atomicAdd(&g_cacc[b][m],r); }
    __threadfence();
    gridBarrier(64);
    if(blockIdx.x==0){
        int t = threadIdx.x;
        if(t<BB){
            int bb = t;
            double N = (double)NPIX;
            double mu[3]; for(int i=0;i<3;i++){ mu[i]=vloadd(&g_cacc[bb][i])/N; g_mean3[bb][i]=mu[i]; }
            double C[9];
            C[0]=vloadd(&g_cacc[bb][3])/N-mu[0]*mu[0]; C[1]=vloadd(&g_cacc[bb][4])/N-mu[0]*mu[1]; C[2]=vloadd(&g_cacc[bb][5])/N-mu[0]*mu[2];
            C[4]=vloadd(&g_cacc[bb][6])/N-mu[1]*mu[1]; C[5]=vloadd(&g_cacc[bb][7])/N-mu[1]*mu[2]; C[8]=vloadd(&g_cacc[bb][8])/N-mu[2]*mu[2];
            C[3]=C[1]; C[6]=C[2]; C[7]=C[5];
            {   // ES 2x2 inverse from the same moments
                double c00=C[4]+1e-6, c01=C[5], c11=C[8]+1e-6;
                double det=c00*c11-c01*c01;
                g_esinv[bb][0]=c11/det; g_esinv[bb][1]=-c01/det; g_esinv[bb][2]=c00/det;
                g_esinv[bb][3]=mu[1]; g_esinv[bb][4]=mu[2];
            }
            for(int i=0;i<9;i++) C[i] = C[i] > 1e-8 ? C[i] : 1e-8;   // elementwise max, matches reference
            double e[3], V[9];
            eigh3(C, e, V);
            for(int i=0;i<3;i++) for(int j=0;j<3;j++){
                double ssum=0; for(int k2=0;k2<3;k2++) ssum += V[i*3+k2]*(1.0/sqrt(e[k2]))*V[j*3+k2];
                g_wwh[bb][i*3+j]=ssum;
            }
            for(int i=0;i<9;i++) g_cacc[bb][i]=0.0;
        }
        __syncthreads();
        if(t < BB*NDIR){
            int bb = t / NDIR, d = t % NDIR;
            float a0=arand[(bb*NDIR+d)*3+0], a1=arand[(bb*NDIR+d)*3+1], a2=arand[(bb*NDIR+d)*3+2];
            float nr = sqrtf(a0*a0+a1*a1+a2*a2) + 1e-12f;
            double an[3]={a0/nr,a1/nr,a2/nr};
            for(int jj=0;jj<3;jj++){
                double ssum=0; for(int i=0;i<3;i++) ssum += g_wwh[bb][jj*3+i]*an[i];
                g_cdir[(bb*NDIR+d)*3+jj]=(float)ssum;
            }
        }
    }
}

__global__ void kKurtAcc(){
    int b = blockIdx.z, g8 = blockIdx.y*8;
    int lane = threadIdx.x & 31;
    float md[3], sd[3], mn[3];
    for(int f=0;f<3;f++){ md[f]=g_sv[b*3+f]; sd[f]=g_sv[6+b*3+f]*1.4826f+1e-8f; mn[f]=(float)g_mean3[b][f]; }
    float c[8][3];
    for(int d=0;d<8;d++) for(int j=0;j<3;j++) c[d][j]=g_cdir[(b*NDIR+g8+d)*3+j];
    float acc[32];
    for(int i=0;i<32;i++) acc[i]=0.f;
    int per = (NPIX + gridDim.x - 1)/gridDim.x;
    int lo = blockIdx.x*per, hi = min(lo+per, NPIX);
    for(int p=lo+threadIdx.x;p<hi;p+=blockDim.x){
        float d0=(g_Lp[b*NPIX+p]-md[0])/sd[0]-mn[0];
        float d1=(g_E [b*NPIX+p]-md[1])/sd[1]-mn[1];
        float d2=(g_S [b*NPIX+p]-md[2])/sd[2]-mn[2];
        #pragma unroll
        for(int d=0;d<8;d++){
            float z = d0*c[d][0]+d1*c[d][1]+d2*c[d][2];
            float z2=z*z;
            acc[d*4+0]+=z; acc[d*4+1]+=z2; acc[d*4+2]+=z2*z; acc[d*4+3]+=z2*z2;
        }
    }
    __shared__ float sacc[32];
    if(threadIdx.x<32) sacc[threadIdx.x]=0.f;
    __syncthreads();
    #pragma unroll
    for(int v=0; v<32; v++){
        float x = acc[v];
        for(int o=16;o;o>>=1) x += __shfl_down_sync(0xffffffffu,x,o);
        if(lane==0) atomicAdd(&sacc[v], x);
    }
    __syncthreads();
    if(threadIdx.x<32) atomicAdd(&g_dirm[b][g8+threadIdx.x/4][threadIdx.x%4],(double)sacc[threadIdx.x]);
}

__global__ void kKurtPick(){
    int b = threadIdx.x; if(b>=BB) return;
    double N=(double)NPIX, bestv=-1.0; int best=0;
    for(int d=0;d<NDIR;d++){
        double m1=g_dirm[b][d][0]/N, s2=g_dirm[b][d][1]/N, s3=g_dirm[b][d][2]/N, s4=g_dirm[b][d][3]/N;
        double m2=(s2-m1*m1)+1e-12;
        double m4=s4-4.0*m1*s3+6.0*m1*m1*s2-3.0*m1*m1*m1*m1;
        double kurt=fabs(m4/(m2*m2)-3.0);
        if(kurt>bestv){bestv=kurt;best=d;}
    }
    for(int j=0;j<3;j++) g_cbest[b][j]=g_cdir[(b*NDIR+best)*3+j];
    for(int d=0;d<NDIR;d++) for(int m=0;m<4;m++) g_dirm[b][d][m]=0.0;
}

__global__ void kZb(){
    int idx = blockIdx.x*blockDim.x + threadIdx.x;
    int b = idx / NPIX;
    float md0=g_sv[b*3+0], md1=g_sv[b*3+1], md2=g_sv[b*3+2];
    float sd0=g_sv[6+b*3+0]*1.4826f+1e-8f, sd1=g_sv[6+b*3+1]*1.4826f+1e-8f, sd2=g_sv[6+b*3+2]*1.4826f+1e-8f;
    float d0=(g_Lp[idx]-md0)/sd0-(float)g_mean3[b][0];
    float d1=(g_E [idx]-md1)/sd1-(float)g_mean3[b][1];
    float d2=(g_S [idx]-md2)/sd2-(float)g_mean3[b][2];
    g_zb[idx] = d0*g_cbest[b][0]+d1*g_cbest[b][1]+d2*g_cbest[b][2];
}

// ================= persistent EM: 32 blocks, zb cached in registers =================
__global__ void __launch_bounds__(1024,1) kEM(){
    int blk = blockIdx.x;
    int b = blk >> 4, sub = blk & 15;
    const float* zb = g_zb + b*NPIX;
    float x[9];
    int base = sub*(NPIX/16) + threadIdx.x;
    #pragma unroll
    for(int i=0;i<9;i++) x[i] = zb[base + i*1024];
    if(sub==0 && threadIdx.x==0){
        float q25 = g_sv[12+4*b] + 0.75f*(g_sv[13+4*b]-g_sv[12+4*b]);
        float q75 = g_sv[14+4*b] + 0.25f*(g_sv[15+4*b]-g_sv[14+4*b]);
        vstored(&g_empar[b][0], q25); vstored(&g_empar[b][1], q75);
        vstored(&g_empar[b][2], 1.0); vstored(&g_empar[b][3], 1.0);
        vstored(&g_empar[b][4], 0.5); vstored(&g_empar[b][5], 0.5);
    }
    __threadfence();
    gridBarrier(EMB);
    for(int it=0; it<9; it++){
        float mu0=(float)vloadd(&g_empar[b][0]), mu1=(float)vloadd(&g_empar[b][1]);
        float v0=(float)vloadd(&g_empar[b][2])+1e-6f, v1=(float)vloadd(&g_empar[b][3])+1e-6f;
        float lw0=-0.5f*logf(v0)+logf((float)vloadd(&g_empar[b][4])+1e-8f);
        float lw1=-0.5f*logf(v1)+logf((float)vloadd(&g_empar[b][5])+1e-8f);
        float iv0=0.5f/v0, iv1=0.5f/v1;
        float a0=0,a1=0,a2=0,a3=0,a4=0,a5=0;
        #pragma unroll
        for(int i=0;i<9;i++){
            float xx=x[i];
            float lp0=-(xx-mu0)*(xx-mu0)*iv0+lw0;
            float lp1=-(xx-mu1)*(xx-mu1)*iv1+lw1;
            float R0=1.f/(1.f+expf(lp1-lp0));
            float R1=1.f/(1.f+expf(lp0-lp1));
            a0+=R0; a1+=R0*xx; a2+=R0*xx*xx;
            a3+=R1; a4+=R1*xx; a5+=R1*xx*xx;
        }
        double s[6]={a0,a1,a2,a3,a4,a5};
        for(int m=0;m<6;m++){
            double r=blockReduceD(s[m]);
            if(threadIdx.x==0) atomicAdd(&g_emacc[b][m],r);
        }
        __threadfence();
        gridBarrier(EMB);
        if(sub==0 && threadIdx.x==0){
            for(int k=0;k<2;k++){
                double Sr=vloadd(&g_emacc[b][k*3]), Sx=vloadd(&g_emacc[b][k*3+1]), Sxx=vloadd(&g_emacc[b][k*3+2]);
                double den=Sr+1e-8, mu=Sx/den;
                double var=(Sxx-2.0*mu*Sx+mu*mu*Sr)/den+1e-6;
                vstored(&g_empar[b][k],mu); vstored(&g_empar[b][2+k],var); vstored(&g_empar[b][4+k],Sr/(double)NPIX);
            }
            for(int m=0;m<6;m++) vstored(&g_emacc[b][m],0.0);
        }
        __threadfence();
        gridBarrier(EMB);
    }
    float mu0=(float)vloadd(&g_empar[b][0]), mu1=(float)vloadd(&g_empar[b][1]);
    float v0=(float)vloadd(&g_empar[b][2])+1e-6f, v1=(float)vloadd(&g_empar[b][3])+1e-6f;
    float lw0=-0.5f*logf(v0)+logf((float)vloadd(&g_empar[b][4])+1e-8f);
    float lw1=-0.5f*logf(v1)+logf((float)vloadd(&g_empar[b][5])+1e-8f);
    float iv0=0.5f/v0, iv1=0.5f/v1;
    #pragma unroll
    for(int i=0;i<9;i++){
        float xx=x[i];
        float lp0=-(xx-mu0)*(xx-mu0)*iv0+lw0;
        float lp1=-(xx-mu1)*(xx-mu1)*iv1+lw1;
        float R0=1.f/(1.f+expf(lp1-lp0));
        float R1=1.f/(1.f+expf(lp0-lp1));
        float r0=powf(R0,0.9f), r1=powf(R1,0.9f);
        float ssum=r0+r1+1e-8f;
        int p = base + i*1024;
        g_Ra[(b*2+0)*NPIX+p]=r0/ssum;
        g_Ra[(b*2+1)*NPIX+p]=r1/ssum;
    }
}

// cluster weighted moments (both k) + bin index + global weighted histogram, then inverses + gcdf
// grid: dim3(64, BB) x 256; barrier over 128 blocks.
__global__ void kClusterBin(){
    int b = blockIdx.y;
    __shared__ float sh[64];
    if(threadIdx.x<64) sh[threadIdx.x]=0.f;
    __syncthreads();
    float mn = u2f(g_mm[b][0]), mx = u2f(g_mm[b][1]);
    float inv_rng = 1.f/(mx-mn+1e-8f);
    double a[20];
    for(int i=0;i<20;i++) a[i]=0.0;
    int per = NPIX/64;
    int lo = blockIdx.x*per, hi = lo+per;
    for(int p=lo+threadIdx.x;p<hi;p+=blockDim.x){
        float w0=g_Ra[(b*2+0)*NPIX+p], w1=g_Ra[(b*2+1)*NPIX+p];
        float lpv=g_Lp[b*NPIX+p];
        double x0=lpv, x1=g_E[b*NPIX+p], x2=g_S[b*NPIX+p];
        a[0]+=w0; a[1]+=w0*x0; a[2]+=w0*x1; a[3]+=w0*x2;
        a[4]+=w0*x0*x0; a[5]+=w0*x0*x1; a[6]+=w0*x0*x2;
        a[7]+=w0*x1*x1; a[8]+=w0*x1*x2; a[9]+=w0*x2*x2;
        a[10]+=w1; a[11]+=w1*x0; a[12]+=w1*x1; a[13]+=w1*x2;
        a[14]+=w1*x0*x0; a[15]+=w1*x0*x1; a[16]+=w1*x0*x2;
        a[17]+=w1*x1*x1; a[18]+=w1*x1*x2; a[19]+=w1*x2*x2;
        float ln = (lpv-mn)*inv_rng;
        ln = fminf(fmaxf(ln,0.f),1.f);
        int c = (int)(ln*32.f); c = c<0?0:(c>31?31:c);
        g_idxb[b*NPIX+p] = (unsigned char)c;
        atomicAdd(&sh[c],    w0);
        atomicAdd(&sh[32+c], w1);
    }
    for(int m=0;m<20;m++){
        double r=blockReduceD(a[m]);
        if(threadIdx.x==0) atomicAdd(&g_clacc[b][m/10][m%10],r);
    }
    __syncthreads();
    if(threadIdx.x<64 && sh[threadIdx.x]!=0.f)
        atomicAdd(&g_ghist[b][threadIdx.x>>5][threadIdx.x&31],(double)sh[threadIdx.x]);
    __threadfence();
    gridBarrier(64*BB);
    if(blockIdx.x==0 && blockIdx.y==0){
        int t = threadIdx.x;
        if(t<4){
            int bb=t>>1, k=t&1;
            double A[10];
            for(int i=0;i<10;i++) A[i]=vloadd(&g_clacc[bb][k][i]);
            double Ws = A[0] + 1e-8;
            double mu[3] = {A[1]/Ws, A[2]/Ws, A[3]/Ws};
            double Sx[3] = {A[1], A[2], A[3]};
            double Sxx[9] = {A[4],A[5],A[6], A[5],A[7],A[8], A[6],A[8],A[9]};
            double C[9];
            for(int i=0;i<3;i++) for(int j2=0;j2<3;j2++)
                C[i*3+j2] = (Sxx[i*3+j2] - mu[i]*Sx[j2] - mu[j2]*Sx[i] + A[0]*mu[i]*mu[j2])/Ws + ((i==j2)?1e-6:0.0);
            double I[9]; inv3(C, I);
            for(int i=0;i<9;i++) g_clinv[bb][k][i]=I[i];
            for(int i=0;i<3;i++) g_clmu[bb][k][i]=mu[i];
            for(int i=0;i<10;i++) g_clacc[bb][k][i]=0.0;
            // gcdf for (bb,k)
            double tot=0; for(int c=0;c<32;c++) tot += vloadd(&g_ghist[bb][k][c]);
            double cum=0;
            for(int c=0;c<32;c++){ cum += vloadd(&g_ghist[bb][k][c])/(tot+1e-8); g_gcdf[bb][k][c]=(float)cum; g_ghist[bb][k][c]=0.0; }
            if(k==0){ g_mm[bb][0]=0xFFFFFFFFu; g_mm[bb][1]=0u; }
        }
    }
}

// DM (k==0 plane threads) fused with horizontal box pass
__global__ void kDMBoxH(){
    int bk = blockIdx.y; int b=bk>>1, k=bk&1;
    int p = blockIdx.x*blockDim.x + threadIdx.x;
    int y = p / WW, x = p % WW;
    float s0=0.f,s1=0.f,s2=0.f;
    int lo = max(x-7,0), hi = min(x+7,WW-1);
    for(int xx=lo;xx<=hi;xx++){
        float r = g_Ra[bk*NPIX + y*WW + xx];
        float l = g_Lp[b*NPIX + y*WW + xx];
        s0+=r; s1+=r*l; s2+=r*l*l;
    }
    g_t0[bk*NPIX+p]=s0; g_t1[bk*NPIX+p]=s1; g_t2[bk*NPIX+p]=s2;
    if(k==0){
        int idx = b*NPIX + p;
        float X0=g_Lp[idx], X1=g_E[idx], X2=g_S[idx];
        float ra0=g_Ra[(b*2+0)*NPIX+p], ra1=g_Ra[(b*2+1)*NPIX+p];
        float ssum = ra0+ra1+2e-8f;
        float DM=0.f;
        for(int kk=0;kk<2;kk++){
            float xm0=X0-(float)g_clmu[b][kk][0];
            float xm1=X1-(float)g_clmu[b][kk][1];
            float xm2=X2-(float)g_clmu[b][kk][2];
            const double* I=g_clinv[b][kk];
            float q = xm0*xm0*(float)I[0] + xm1*xm1*(float)I[4] + xm2*xm2*(float)I[8]
                    + 2.f*xm0*xm1*(float)I[1] + 2.f*xm0*xm2*(float)I[2] + 2.f*xm1*xm2*(float)I[5];
            float Dk = sqrtf(q + 1e-8f);
            float Rt = ((kk==0?ra0:ra1)+1e-8f)/ssum;
            DM += Rt*Dk;
        }
        g_DM[idx]=DM;
    }
}

__global__ void kBoxV(){
    int bk = blockIdx.y; int b=bk>>1;
    int p = blockIdx.x*blockDim.x + threadIdx.x;
    int y = p / WW, x = p % WW;
    float s0=0.f,s1=0.f,s2=0.f;
    int lo = max(y-7,0), hi = min(y+7,HH-1);
    for(int yy=lo;yy<=hi;yy++){
        s0+=g_t0[bk*NPIX+yy*WW+x]; s1+=g_t1[bk*NPIX+yy*WW+x]; s2+=g_t2[bk*NPIX+yy*WW+x];
    }
    float cy = (float)(min(y+8,HH)-max(y-7,0));
    float cx = (float)(min(x+8,WW)-max(x-7,0));
    float c = cy*cx;
    float a0=s0/c, a1=s1/c, a2=s2/c;
    float den = a0 + 1e-8f;
    float mu = a1/den;
    float vb = fmaxf(a2/den - mu*mu, 1e-8f);
    g_lla[bk*NPIX+p] = fabsf(g_Lp[b*NPIX+p]-mu)/(sqrtf(vb)+1e-8f);
    g_den[bk*NPIX+p] = a0;
}

// vertical sliding per-column histogram in BIN-PREFIX form, segmented along y
__global__ void kColHist(){
    int bk = blockIdx.z; int b=bk>>1;
    int warp = threadIdx.x>>5, lane = threadIdx.x&31;
    int x = blockIdx.x*4 + warp;
    int y0 = blockIdx.y*SEG;
    const float* rk = g_Ra + bk*NPIX;
    const unsigned char* bi = g_idxb + b*NPIX;
    float P = 0.f;
    for(int r=y0-7; r<=y0+6; r++){
        if(r>=0){ float v=rk[r*WW+x]; int bn=bi[r*WW+x]; if(lane>=bn) P+=v; }
    }
    for(int y=y0; y<y0+SEG; y++){
        int ra=y+7;
        if(ra<HH){ float v=rk[ra*WW+x]; int bn=bi[ra*WW+x]; if(lane>=bn) P+=v; }
        g_colsum[((size_t)(bk*HH+y)*WW + x)*32 + lane] = P;
        int rr=y-7;
        if(rr>=0){ float v=rk[rr*WW+x]; int bn=bi[rr*WW+x]; if(lane>=bn) P-=v; }
    }
}

// horizontal sliding sum of prefix-columns -> local CDF; segmented along x
__global__ void kGLD(){
    int bk = blockIdx.z; int b=bk>>1, k=bk&1;
    int warp = threadIdx.x>>5, lane = threadIdx.x&31;
    int y = blockIdx.x*4 + warp;
    int x0 = blockIdx.y*SEG;
    const float* cs = g_colsum + (size_t)(bk*HH+y)*WW*32;
    float gc = g_gcdf[b][k][lane];
    float S = 0.f;
    for(int xx=x0-7; xx<=x0+6; xx++) if(xx>=0) S += cs[xx*32+lane];
    float cy = (float)(min(y+8,HH)-max(y-7,0));
    for(int x=x0; x<x0+SEG; x++){
        if(x+7<WW) S += cs[(x+7)*32+lane];
        float cx = (float)(min(x+8,WW)-max(x-7,0));
        float den = g_den[bk*NPIX + y*WW+x] + 1e-8f;
        float diff = fabsf(S/(cy*cx)/den - gc);
        for(int o=16;o;o>>=1) diff += __shfl_down_sync(0xffffffffu,diff,o);
        if(lane==0) g_gld[bk*NPIX + y*WW+x] = diff*(1.f/32.f);
        if(x-7>=0) S -= cs[(x-7)*32+lane];
    }
}

__global__ void kGamma(){
    int idx = blockIdx.x*blockDim.x + threadIdx.x;
    int b = idx / NPIX, p = idx % NPIX;
    float gamma = 1.f;
    for(int k=0;k<2;k++){
        int s = b*2+k;
        float zl = (g_lla[s*NPIX+p]-g_sv[20+s])/(g_sv[24+s]*1.4826f+1e-8f);
        float zg = (g_gld[s*NPIX+p]-g_sv[28+s])/(g_sv[32+s]*1.4826f+1e-8f);
        gamma += g_Ra[s*NPIX+p]*(0.5f*softplusf(zl)+0.5f*softplusf(zg));
    }
    float mdE=g_sv[b*3+1], mdS=g_sv[b*3+2];
    float sdE=g_sv[6+b*3+1]*1.4826f+1e-8f, sdS=g_sv[6+b*3+2]*1.4826f+1e-8f;
    float dE=(g_E[idx]-mdE)/sdE-(float)g_esinv[b][3];
    float dS=(g_S[idx]-mdS)/sdS-(float)g_esinv[b][4];
    float d2 = dE*dE*(float)g_esinv[b][0] + 2.f*dE*dS*(float)g_esinv[b][1] + dS*dS*(float)g_esinv[b][2];
    float Rs = expf(-0.5f*d2);
    g_La[idx] = fmaxf(g_DM[idx]*gamma*(1.f-Rs), 0.f);
}

__global__ void kFinal(float* __restrict__ out){
    int idx = blockIdx.x*blockDim.x + threadIdx.x;
    int b = idx / NPIX;
    float q1 = g_sv[36+4*b] + 0.55f*(g_sv[37+4*b]-g_sv[36+4*b]);
    float q9 = g_sv[38+4*b] + 0.45f*(g_sv[39+4*b]-g_sv[38+4*b]);
    float v = (g_La[idx]-q1)/(q9-q1+1e-8f);
    out[BN + idx] = fminf(fmaxf(v,0.f),1.f);   // output #2
}

// ======================= host =======================
extern "C" void kernel_launch(void* const* d_in, const int* in_sizes, int n_in,
                              void* d_out, int out_size){
    const float* lab   = (const float*)d_in[0];
    const float* arand = (const float*)d_in[1];
    float* out = (float*)d_out;
    const int EB = (BN+255)/256;      // 1152 (exact)

    kSobel<<<EB,256>>>(lab);
    kE<<<EB,256>>>(lab);
    kSolve<<<1,32>>>();
    kLperp<<<EB,256>>>(lab,out);

    selFused<<<6,1024>>>(0);              // med+MAD of Lp,E,S
    kCovEighCdir<<<64,256>>>(arand);      // cov + eigh + ES-inv + whitened dirs
    kKurtAcc<<<dim3(32,16,BB),256>>>();
    kKurtPick<<<1,32>>>();
    kZb<<<EB,256>>>();

    selFused<<<4,1024>>>(6);              // z_best quartile brackets
    kEM<<<EMB,1024>>>();                  // persistent EM -> Ra

    kClusterBin<<<dim3(64,BB),256>>>();   // cluster moments + binidx + ghist -> inv + gcdf
    kDMBoxH<<<dim3(576,4),256>>>();
    kBoxV<<<dim3(576,4),256>>>();
    selFused<<<4,1024>>>(10);             // LLA med+MAD

    kColHist<<<dim3(96,8,4),128>>>();
    kGLD<<<dim3(96,8,4),128>>>();
    selFused<<<4,1024>>>(14);             // GLD med+MAD

    kGamma<<<EB,256>>>();
    selFused<<<4,1024>>>(18);             // L_anom 1%/99% brackets
    kFinal<<<EB,256>>>(out);
}

// round 7
// speedup vs baseline: 1.5175x; 1.0349x over previous
#include <cuda_runtime.h>
#include <math.h>

#define HH 384
#define WW 384
#define NPIX (HH*WW)          // 147456
#define BB 2
#define BN (BB*NPIX)          // 294912
#define NDIR 128
#define EMB 32
#define SELG 16
#define GTY 24

// ======================= scratch buffers =======================
__device__ float g_E[BN];
__device__ float g_S[BN];
__device__ float g_Lp[BN];
__device__ float g_zb[BN];
__device__ float g_Ra[2*BN];     // [(b*2+k)*NPIX+n]
__device__ float g_DM[BN];
__device__ float g_t0[2*BN], g_t1[2*BN], g_t2[2*BN];
__device__ float g_lla[2*BN];
__device__ float g_den[2*BN];
__device__ float g_gld[2*BN];
__device__ float g_La[BN];
__device__ unsigned char g_idxb[BN];
__device__ unsigned g_jh[8*6*2048];     // cooperative select histograms

// ======================= small state =======================
__device__ float    g_sv[64];
__device__ unsigned g_mm[BB][2] = {{0xFFFFFFFFu,0u},{0xFFFFFFFFu,0u}};
__device__ double   g_reg[BB][5];
__device__ double   g_beta[BB][2];
__device__ double   g_cacc[BB][9];
__device__ double   g_mean3[BB][3];
__device__ double   g_wwh[BB][9];
__device__ float    g_cdir[BB*NDIR*3];
__device__ float    g_cbest[BB][3];
__device__ double   g_dirm[BB][NDIR][4];
__device__ double   g_emacc2[9][BB][6];
__device__ double   g_clacc[BB][2][10];
__device__ double   g_clmu[BB][2][3];
__device__ double   g_clinv[BB][2][9];
__device__ double   g_ghist[BB][2][32];
__device__ float    g_gcdf[BB][2][32];
__device__ double   g_esinv[BB][6];

// grid-wide barrier (monotonic generation; arrive self-resets)
__device__ int g_barArrive = 0;
__device__ int g_barGen = 0;

static __device__ __forceinline__ void gridBarrier(int nb){
    __threadfence();
    __syncthreads();
    if(threadIdx.x==0){
        int gen = *(volatile int*)&g_barGen;
        if(atomicAdd(&g_barArrive,1)==nb-1){
            g_barArrive = 0;
            __threadfence();
            *(volatile int*)&g_barGen = gen+1;
        } else {
            while(*(volatile int*)&g_barGen == gen) { }
        }
    }
    __syncthreads();
}

static __device__ __forceinline__ double vloadd(const double* p){ return *(volatile const double*)p; }
static __device__ __forceinline__ float  vloadf(const float* p){ return *(volatile const float*)p; }

// ======================= helpers =======================
static __device__ __forceinline__ unsigned f2u(float f){
    unsigned u = __float_as_uint(f);
    return (u & 0x80000000u) ? ~u : (u | 0x80000000u);
}
static __device__ __forceinline__ float u2f(unsigned u){
    unsigned v = (u & 0x80000000u) ? (u & 0x7FFFFFFFu) : ~u;
    return __uint_as_float(v);
}
static __device__ __forceinline__ float softplusf(float x){
    float t = log1pf(expf(-fabsf(x)));
    return x >= 0.f ? x + t : t;
}
static __device__ double blockReduceD(double v){
    __shared__ double sh[32];
    int lane = threadIdx.x & 31, wid = threadIdx.x >> 5;
    for (int o=16;o;o>>=1) v += __shfl_down_sync(0xffffffffu, v, o);
    if (lane==0) sh[wid] = v;
    __syncthreads();
    int nw = (blockDim.x + 31) >> 5;
    v = (threadIdx.x < nw) ? sh[threadIdx.x] : 0.0;
    if (wid==0) for (int o=16;o;o>>=1) v += __shfl_down_sync(0xffffffffu, v, o);
    __syncthreads();
    return v;
}
static __device__ void eigh3(const double* A, double* e, double* V){
    double a[9]; for(int i=0;i<9;i++) a[i]=A[i];
    for(int i=0;i<9;i++) V[i] = (i%4==0)?1.0:0.0;
    for(int sweep=0;sweep<40;sweep++){
        double off = fabs(a[1])+fabs(a[2])+fabs(a[5]);
        if(off < 1e-300) break;
        for(int p=0;p<2;p++) for(int q=p+1;q<3;q++){
            double apq=a[p*3+q];
            if(fabs(apq) < 1e-300) continue;
            double app=a[p*3+p], aqq=a[q*3+q];
            double th=(aqq-app)/(2.0*apq);
            double t=(th>=0?1.0:-1.0)/(fabs(th)+sqrt(th*th+1.0));
            double c=1.0/sqrt(t*t+1.0), s=t*c;
            for(int i=0;i<3;i++){ double x=a[i*3+p],y=a[i*3+q]; a[i*3+p]=c*x-s*y; a[i*3+q]=s*x+c*y; }
            for(int i=0;i<3;i++){ double x=a[p*3+i],y=a[q*3+i]; a[p*3+i]=c*x-s*y; a[q*3+i]=s*x+c*y; }
            for(int i=0;i<3;i++){ double x=V[i*3+p],y=V[i*3+q]; V[i*3+p]=c*x-s*y; V[i*3+q]=s*x+c*y; }
        }
    }
    e[0]=a[0]; e[1]=a[4]; e[2]=a[8];
}
static __device__ void inv3(const double* m, double* inv){
    double a=m[0],b=m[1],c=m[2],d=m[3],e=m[4],f=m[5],g=m[6],h=m[7],i=m[8];
    double A=e*i-f*h, B=c*h-b*i, C=b*f-c*e;
    double D=f*g-d*i, E=a*i-c*g, F=c*d-a*f;
    double G=d*h-e*g, Hh=b*g-a*h, I=a*e-b*d;
    double det=a*A+b*D+c*G, id=1.0/det;
    inv[0]=A*id; inv[1]=B*id; inv[2]=C*id;
    inv[3]=D*id; inv[4]=E*id; inv[5]=F*id;
    inv[6]=G*id; inv[7]=Hh*id; inv[8]=I*id;
}

// ======================= cooperative radix select =======================
// jobs: {kind, type, b, rank, slotA, slotB}
__device__ const int g_seljobs[22*6] = {
 0,0,0,73727,0,6,   0,1,0,73727,1,7,   0,2,0,73727,2,8,
 0,0,1,73727,3,9,   0,1,1,73727,4,10,  0,2,1,73727,5,11,
 1,3,0,36863,12,13,  1,3,0,110591,14,15,  1,3,1,36863,16,17,  1,3,1,110591,18,19,
 0,4,0,73727,20,24,  0,5,0,73727,21,25,  0,4,1,73727,22,26,  0,5,1,73727,23,27,
 0,6,0,73727,28,32,  0,7,0,73727,29,33,  0,6,1,73727,30,34,  0,7,1,73727,31,35,
 1,8,0,1474,36,37,  1,8,0,145980,38,39,  1,8,1,1474,40,41,  1,8,1,145980,42,43
};

static __device__ const float* selSrc(int type, int b){
    switch(type){
        case 0: return g_Lp + b*NPIX;
        case 1: return g_E  + b*NPIX;
        case 2: return g_S  + b*NPIX;
        case 3: return g_zb + b*NPIX;
        case 4: return g_lla + (b*2+0)*NPIX;
        case 5: return g_lla + (b*2+1)*NPIX;
        case 6: return g_gld + (b*2+0)*NPIX;
        case 7: return g_gld + (b*2+1)*NPIX;
        default: return g_La + b*NPIX;
    }
}

static __device__ void coopZero(int njobs, int nbTot){
    int total = njobs*6*2048;
    for(int i=blockIdx.x*blockDim.x+threadIdx.x; i<total; i+=nbTot*blockDim.x)
        g_jh[i]=0u;
}

// 3-pass (11/11/10 bit) cooperative select across SELG blocks per job.
static __device__ float coopSel(const float4* __restrict__ src4, float ref, int useAbs, unsigned rank,
                                int jobLocal, int passBase, int chunk, int nbTot){
    __shared__ unsigned sh[2048];
    __shared__ unsigned sres[2];
    unsigned pref=0, rk=rank;
    for(int pass=0; pass<3; pass++){
        unsigned* hist = g_jh + (jobLocal*6+passBase+pass)*2048;
        int nbin = (pass==2)?1024:2048;
        for(int i=threadIdx.x;i<nbin;i+=blockDim.x) sh[i]=0u;
        __syncthreads();
        int per = (NPIX/4)/SELG;      // 2304
        int lo = chunk*per;
        for(int i=lo+threadIdx.x;i<lo+per;i+=blockDim.x){
            float4 v4 = src4[i];
            float vv[4]={v4.x,v4.y,v4.z,v4.w};
            #pragma unroll
            for(int c=0;c<4;c++){
                float v=vv[c]; if(useAbs) v=fabsf(v-ref);
                unsigned key=f2u(v);
                if(pass==0) atomicAdd(&sh[key>>21],1u);
                else if(pass==1){ if((key>>21)==(pref>>21)) atomicAdd(&sh[(key>>10)&2047u],1u); }
                else { if((key>>10)==(pref>>10)) atomicAdd(&sh[key&1023u],1u); }
            }
        }
        __syncthreads();
        for(int i=threadIdx.x;i<nbin;i+=blockDim.x) if(sh[i]) atomicAdd(&hist[i],sh[i]);
        gridBarrier(nbTot);
        if(threadIdx.x<32){
            int lane=threadIdx.x, perl=nbin>>5;
            unsigned s=0;
            for(int i=0;i<perl;i++) s+=hist[lane*perl+i];
            unsigned cum=s;
            #pragma unroll
            for(int o=1;o<32;o<<=1){ unsigned t=__shfl_up_sync(0xffffffffu,cum,o); if(lane>=o) cum+=t; }
            unsigned prev=cum-s;
            if(prev<=rk && rk<cum){
                unsigned rr=rk-prev; int bin=lane*perl;
                for(int i=0;i<perl;i++){ unsigned c=hist[lane*perl+i]; if(rr<c){ bin=lane*perl+i; break;} rr-=c; }
                sres[0]=(pass==0)? ((unsigned)bin<<21) : (pass==1)? (pref|((unsigned)bin<<10)) : (pref|(unsigned)bin);
                sres[1]=rr;
            }
        }
        __syncthreads();
        pref=sres[0]; rk=sres[1];
        __syncthreads();
    }
    return u2f(pref);
}

__global__ void __launch_bounds__(1024,1) selCoop(int jobBase, int njobs){
    int nbTot = njobs*SELG;
    int job = blockIdx.x/SELG, chunk = blockIdx.x%SELG;
    coopZero(njobs, nbTot);
    gridBarrier(nbTot);
    const int* jb = &g_seljobs[(jobBase+job)*6];
    const float4* src = (const float4*)selSrc(jb[1], jb[2]);
    if(jb[0]==0){
        float med = coopSel(src,0.f,0,(unsigned)jb[3],job,0,chunk,nbTot);
        if(chunk==0&&threadIdx.x==0) g_sv[jb[4]]=med;
        float mad = coopSel(src,med,1,(unsigned)jb[3],job,3,chunk,nbTot);
        if(chunk==0&&threadIdx.x==0) g_sv[jb[5]]=mad;
    } else {
        float v0 = coopSel(src,0.f,0,(unsigned)jb[3],job,0,chunk,nbTot);
        if(chunk==0&&threadIdx.x==0) g_sv[jb[4]]=v0;
        float v1 = coopSel(src,0.f,0,(unsigned)jb[3]+1u,job,3,chunk,nbTot);
        if(chunk==0&&threadIdx.x==0) g_sv[jb[5]]=v1;
    }
}

// ======================= pipeline kernels =======================
// fused Sobel + avg3 + regression accumulation, tiled in shared memory
__global__ void __launch_bounds__(256) kSobelE(const float* __restrict__ lab){
    __shared__ float sL[20][20];
    __shared__ float sP[18][18];
    int b = blockIdx.z;
    int x0 = blockIdx.x*16, y0 = blockIdx.y*16;
    int tid = threadIdx.x;
    int tx = tid & 15, ty = tid >> 4;
    const float* L = lab + (size_t)b*3*NPIX;
    for(int i=tid;i<400;i+=256){
        int jj=i/20, ii=i%20;
        int yy=y0-2+jj, xx=x0-2+ii;
        sL[jj][ii] = (yy>=0&&yy<HH&&xx>=0&&xx<WW) ? L[yy*WW+xx] : 0.f;
    }
    __syncthreads();
    for(int i=tid;i<324;i+=256){
        int jj=i/18, ii=i%18;
        int py=y0-1+jj, px=x0-1+ii;
        float v=0.f;
        if(py>=0&&py<HH&&px>=0&&px<WW){
            float l00=sL[jj][ii],   l01=sL[jj][ii+1],   l02=sL[jj][ii+2];
            float l10=sL[jj+1][ii],                     l12=sL[jj+1][ii+2];
            float l20=sL[jj+2][ii], l21=sL[jj+2][ii+1], l22=sL[jj+2][ii+2];
            float gx = -l00 + l02 - 2.f*l10 + 2.f*l12 - l20 + l22;
            float gy = -l00 - 2.f*l01 - l02 + l20 + 2.f*l21 + l22;
            v = gx*gx + gy*gy;
        }
        sP[jj][ii]=v;
    }
    __syncthreads();
    int y=y0+ty, x=x0+tx;
    int p = y*WW+x, idx = b*NPIX+p;
    float s = sP[ty][tx]  +sP[ty][tx+1]  +sP[ty][tx+2]
            + sP[ty+1][tx]+sP[ty+1][tx+1]+sP[ty+1][tx+2]
            + sP[ty+2][tx]+sP[ty+2][tx+1]+sP[ty+2][tx+2];
    float E = s/9.f;
    float av = L[NPIX+p], bv = L[2*NPIX+p];
    float S = sqrtf(av*av+bv*bv+1e-8f);
    g_E[idx]=E; g_S[idx]=S;
    double e=E, sv=S, l=L[p];
    double r;
    r=blockReduceD(e*e);  if(tid==0) atomicAdd(&g_reg[b][0],r);
    r=blockReduceD(e*sv); if(tid==0) atomicAdd(&g_reg[b][1],r);
    r=blockReduceD(sv*sv);if(tid==0) atomicAdd(&g_reg[b][2],r);
    r=blockReduceD(e*l);  if(tid==0) atomicAdd(&g_reg[b][3],r);
    r=blockReduceD(sv*l); if(tid==0) atomicAdd(&g_reg[b][4],r);
}

__global__ void kSolve(){
    int b = threadIdx.x; if(b>=BB) return;
    double ee=g_reg[b][0]+1e-6, es=g_reg[b][1], ss=g_reg[b][2]+1e-6;
    double el=g_reg[b][3], sl=g_reg[b][4];
    double det = ee*ss - es*es;
    g_beta[b][0] = (ss*el - es*sl)/det;
    g_beta[b][1] = (ee*sl - es*el)/det;
    for(int i=0;i<5;i++) g_reg[b][i]=0.0;
}

__global__ void kLperp(const float* __restrict__ lab, float* __restrict__ out){
    int idx = blockIdx.x*blockDim.x + threadIdx.x;
    int b = idx / NPIX, p = idx % NPIX;
    float v = lab[(size_t)b*3*NPIX+p] - (float)g_beta[b][0]*g_E[idx] - (float)g_beta[b][1]*g_S[idx];
    g_Lp[idx] = v;
    out[idx] = v;   // output #1
    unsigned k = f2u(v);
    __shared__ unsigned smn[256], smx[256];
    smn[threadIdx.x]=k; smx[threadIdx.x]=k;
    __syncthreads();
    for(int o=128;o>0;o>>=1){
        if(threadIdx.x<o){ smn[threadIdx.x]=min(smn[threadIdx.x],smn[threadIdx.x+o]);
                           smx[threadIdx.x]=max(smx[threadIdx.x],smx[threadIdx.x+o]); }
        __syncthreads();
    }
    if(threadIdx.x==0){ atomicMin(&g_mm[b][0],smn[0]); atomicMax(&g_mm[b][1],smx[0]); }
}

// robust-z cov + eigh + whitening + ES inverse + whitened directions
__global__ void kCovEighCdir(const float* __restrict__ arand){
    int b = blockIdx.x >> 5, chunk = blockIdx.x & 31;
    float md[3], sd[3];
    for(int f=0;f<3;f++){ md[f]=g_sv[b*3+f]; sd[f]=g_sv[6+b*3+f]*1.4826f+1e-8f; }
    double a[9]={0,0,0,0,0,0,0,0,0};
    int per = NPIX/32;
    int lo = chunk*per, hi = lo+per;
    for(int p=lo+threadIdx.x;p<hi;p+=blockDim.x){
        float z0=(g_Lp[b*NPIX+p]-md[0])/sd[0];
        float z1=(g_E [b*NPIX+p]-md[1])/sd[1];
        float z2=(g_S [b*NPIX+p]-md[2])/sd[2];
        a[0]+=z0; a[1]+=z1; a[2]+=z2;
        a[3]+=(double)z0*z0; a[4]+=(double)z0*z1; a[5]+=(double)z0*z2;
        a[6]+=(double)z1*z1; a[7]+=(double)z1*z2; a[8]+=(double)z2*z2;
    }
    for(int m=0;m<9;m++){ double r=blockReduceD(a[m]); if(threadIdx.x==0) atomicAdd(&g_cacc[b][m],r); }
    gridBarrier(64);
    if(blockIdx.x==0){
        int t = threadIdx.x;
        if(t<BB){
            int bb = t;
            double N = (double)NPIX;
            double mu[3]; for(int i=0;i<3;i++){ mu[i]=vloadd(&g_cacc[bb][i])/N; g_mean3[bb][i]=mu[i]; }
            double C[9];
            C[0]=vloadd(&g_cacc[bb][3])/N-mu[0]*mu[0]; C[1]=vloadd(&g_cacc[bb][4])/N-mu[0]*mu[1]; C[2]=vloadd(&g_cacc[bb][5])/N-mu[0]*mu[2];
            C[4]=vloadd(&g_cacc[bb][6])/N-mu[1]*mu[1]; C[5]=vloadd(&g_cacc[bb][7])/N-mu[1]*mu[2]; C[8]=vloadd(&g_cacc[bb][8])/N-mu[2]*mu[2];
            C[3]=C[1]; C[6]=C[2]; C[7]=C[5];
            {
                double c00=C[4]+1e-6, c01=C[5], c11=C[8]+1e-6;
                double det=c00*c11-c01*c01;
                g_esinv[bb][0]=c11/det; g_esinv[bb][1]=-c01/det; g_esinv[bb][2]=c00/det;
                g_esinv[bb][3]=mu[1]; g_esinv[bb][4]=mu[2];
            }
            for(int i=0;i<9;i++) C[i] = C[i] > 1e-8 ? C[i] : 1e-8;
            double e[3], V[9];
            eigh3(C, e, V);
            for(int i=0;i<3;i++) for(int j=0;j<3;j++){
                double ssum=0; for(int k2=0;k2<3;k2++) ssum += V[i*3+k2]*(1.0/sqrt(e[k2]))*V[j*3+k2];
                g_wwh[bb][i*3+j]=ssum;
            }
            for(int i=0;i<9;i++) g_cacc[bb][i]=0.0;
        }
        __syncthreads();
        if(t < BB*NDIR){
            int bb = t / NDIR, d = t % NDIR;
            float a0=arand[(bb*NDIR+d)*3+0], a1=arand[(bb*NDIR+d)*3+1], a2=arand[(bb*NDIR+d)*3+2];
            float nr = sqrtf(a0*a0+a1*a1+a2*a2) + 1e-12f;
            double an[3]={a0/nr,a1/nr,a2/nr};
            for(int jj=0;jj<3;jj++){
                double ssum=0; for(int i=0;i<3;i++) ssum += g_wwh[bb][jj*3+i]*an[i];
                g_cdir[(bb*NDIR+d)*3+jj]=(float)ssum;
            }
        }
    }
}

// kurtosis moments: pixels in registers, all 128 dirs per block
__global__ void __launch_bounds__(256) kKurtAcc(){
    int b = blockIdx.y, chunk = blockIdx.x;
    __shared__ float scd[NDIR*3];
    __shared__ float sacc[NDIR*4];
    for(int i=threadIdx.x;i<NDIR*3;i+=256) scd[i]=g_cdir[b*NDIR*3+i];
    for(int i=threadIdx.x;i<NDIR*4;i+=256) sacc[i]=0.f;
    float md[3], sd[3], mn[3];
    for(int f=0;f<3;f++){ md[f]=g_sv[b*3+f]; sd[f]=g_sv[6+b*3+f]*1.4826f+1e-8f; mn[f]=(float)g_mean3[b][f]; }
    int base = b*NPIX + chunk*(NPIX/64);
    float d0[9], d1[9], d2[9];
    #pragma unroll
    for(int i=0;i<9;i++){
        int p = base + i*256 + threadIdx.x;
        d0[i]=(g_Lp[p]-md[0])/sd[0]-mn[0];
        d1[i]=(g_E [p]-md[1])/sd[1]-mn[1];
        d2[i]=(g_S [p]-md[2])/sd[2]-mn[2];
    }
    __syncthreads();
    int lane = threadIdx.x & 31;
    for(int d=0;d<NDIR;d++){
        float c0=scd[d*3], c1=scd[d*3+1], c2=scd[d*3+2];
        float s1=0,s2=0,s3=0,s4=0;
        #pragma unroll
        for(int i=0;i<9;i++){
            float z=d0[i]*c0+d1[i]*c1+d2[i]*c2;
            float z2=z*z;
            s1+=z; s2+=z2; s3+=z2*z; s4+=z2*z2;
        }
        for(int o=16;o;o>>=1){
            s1+=__shfl_down_sync(0xffffffffu,s1,o); s2+=__shfl_down_sync(0xffffffffu,s2,o);
            s3+=__shfl_down_sync(0xffffffffu,s3,o); s4+=__shfl_down_sync(0xffffffffu,s4,o);
        }
        if(lane==0){
            atomicAdd(&sacc[d*4+0],s1); atomicAdd(&sacc[d*4+1],s2);
            atomicAdd(&sacc[d*4+2],s3); atomicAdd(&sacc[d*4+3],s4);
        }
    }
    __syncthreads();
    for(int i=threadIdx.x;i<NDIR*4;i+=256)
        atomicAdd(&((double*)g_dirm)[b*NDIR*4+i], (double)sacc[i]);
}

__global__ void kKurtPick(){
    int b = threadIdx.x; if(b>=BB) return;
    double N=(double)NPIX, bestv=-1.0; int best=0;
    for(int d=0;d<NDIR;d++){
        double m1=g_dirm[b][d][0]/N, s2=g_dirm[b][d][1]/N, s3=g_dirm[b][d][2]/N, s4=g_dirm[b][d][3]/N;
        double m2=(s2-m1*m1)+1e-12;
        double m4=s4-4.0*m1*s3+6.0*m1*m1*s2-3.0*m1*m1*m1*m1;
        double kurt=fabs(m4/(m2*m2)-3.0);
        if(kurt>bestv){bestv=kurt;best=d;}
    }
    for(int j=0;j<3;j++) g_cbest[b][j]=g_cdir[(b*NDIR+best)*3+j];
    for(int d=0;d<NDIR;d++) for(int m=0;m<4;m++) g_dirm[b][d][m]=0.0;
}

// phase Z: compute zb inline, then cooperative quartile-bracket selects
__global__ void __launch_bounds__(1024,1) kPhaseZ(){
    int nbTot = 4*SELG;   // 64
    int job = blockIdx.x/SELG, chunk = blockIdx.x%SELG;
    int per = BN/64;      // 4608
    int lo = blockIdx.x*per;
    for(int idx=lo+threadIdx.x; idx<lo+per; idx+=blockDim.x){
        int b = idx / NPIX;
        float md0=g_sv[b*3+0], md1=g_sv[b*3+1], md2=g_sv[b*3+2];
        float sd0=g_sv[6+b*3+0]*1.4826f+1e-8f, sd1=g_sv[6+b*3+1]*1.4826f+1e-8f, sd2=g_sv[6+b*3+2]*1.4826f+1e-8f;
        float d0=(g_Lp[idx]-md0)/sd0-(float)g_mean3[b][0];
        float d1=(g_E [idx]-md1)/sd1-(float)g_mean3[b][1];
        float d2=(g_S [idx]-md2)/sd2-(float)g_mean3[b][2];
        g_zb[idx] = d0*g_cbest[b][0]+d1*g_cbest[b][1]+d2*g_cbest[b][2];
    }
    coopZero(4, nbTot);
    gridBarrier(nbTot);
    const int* jb = &g_seljobs[(6+job)*6];
    const float4* src = (const float4*)selSrc(jb[1], jb[2]);
    float v0 = coopSel(src,0.f,0,(unsigned)jb[3],job,0,chunk,nbTot);
    if(chunk==0&&threadIdx.x==0) g_sv[jb[4]]=v0;
    float v1 = coopSel(src,0.f,0,(unsigned)jb[3]+1u,job,3,chunk,nbTot);
    if(chunk==0&&threadIdx.x==0) g_sv[jb[5]]=v1;
}

// persistent EM: per-iteration accumulator slots (1 barrier/iter), zb in registers
__global__ void __launch_bounds__(1024,1) kEM(){
    int blk = blockIdx.x;
    int b = blk >> 4, sub = blk & 15;
    const float* zb = g_zb + b*NPIX;
    float x[9];
    int base = sub*(NPIX/16) + threadIdx.x;
    #pragma unroll
    for(int i=0;i<9;i++) x[i] = zb[base + i*1024];
    {
        double* acc = (double*)g_emacc2;
        int tot = 9*BB*6;
        for(int i=blk*blockDim.x+threadIdx.x; i<tot; i+=EMB*blockDim.x) acc[i]=0.0;
    }
    float q25 = g_sv[12+4*b] + 0.75f*(g_sv[13+4*b]-g_sv[12+4*b]);
    float q75 = g_sv[14+4*b] + 0.25f*(g_sv[15+4*b]-g_sv[14+4*b]);
    double mu0=q25, mu1=q75, var0=1.0, var1=1.0, pi0=0.5, pi1=0.5;
    gridBarrier(EMB);
    for(int it=0; it<9; it++){
        float m0=(float)mu0, m1=(float)mu1;
        float v0=(float)var0+1e-6f, v1=(float)var1+1e-6f;
        float lw0=-0.5f*logf(v0)+logf((float)pi0+1e-8f);
        float lw1=-0.5f*logf(v1)+logf((float)pi1+1e-8f);
        float iv0=0.5f/v0, iv1=0.5f/v1;
        float a0=0,a1=0,a2=0,a3=0,a4=0,a5=0;
        #pragma unroll
        for(int i=0;i<9;i++){
            float xx=x[i];
            float lp0=-(xx-m0)*(xx-m0)*iv0+lw0;
            float lp1=-(xx-m1)*(xx-m1)*iv1+lw1;
            float R0=1.f/(1.f+expf(lp1-lp0));
            float R1=1.f/(1.f+expf(lp0-lp1));
            a0+=R0; a1+=R0*xx; a2+=R0*xx*xx;
            a3+=R1; a4+=R1*xx; a5+=R1*xx*xx;
        }
        double s[6]={a0,a1,a2,a3,a4,a5};
        for(int m=0;m<6;m++){
            double r=blockReduceD(s[m]);
            if(threadIdx.x==0) atomicAdd(&g_emacc2[it][b][m],r);
        }
        gridBarrier(EMB);
        {
            double Sr0=vloadd(&g_emacc2[it][b][0]), Sx0=vloadd(&g_emacc2[it][b][1]), Sxx0=vloadd(&g_emacc2[it][b][2]);
            double Sr1=vloadd(&g_emacc2[it][b][3]), Sx1=vloadd(&g_emacc2[it][b][4]), Sxx1=vloadd(&g_emacc2[it][b][5]);
            double den0=Sr0+1e-8; mu0=Sx0/den0;
            var0=(Sxx0-2.0*mu0*Sx0+mu0*mu0*Sr0)/den0+1e-6; pi0=Sr0/(double)NPIX;
            double den1=Sr1+1e-8; mu1=Sx1/den1;
            var1=(Sxx1-2.0*mu1*Sx1+mu1*mu1*Sr1)/den1+1e-6; pi1=Sr1/(double)NPIX;
        }
    }
    float m0=(float)mu0, m1=(float)mu1;
    float v0=(float)var0+1e-6f, v1=(float)var1+1e-6f;
    float lw0=-0.5f*logf(v0)+logf((float)pi0+1e-8f);
    float lw1=-0.5f*logf(v1)+logf((float)pi1+1e-8f);
    float iv0=0.5f/v0, iv1=0.5f/v1;
    #pragma unroll
    for(int i=0;i<9;i++){
        float xx=x[i];
        float lp0=-(xx-m0)*(xx-m0)*iv0+lw0;
        float lp1=-(xx-m1)*(xx-m1)*iv1+lw1;
        float R0=1.f/(1.f+expf(lp1-lp0));
        float R1=1.f/(1.f+expf(lp0-lp1));
        float r0=powf(R0,0.9f), r1=powf(R1,0.9f);
        float ssum=r0+r1+1e-8f;
        int p = base + i*1024;
        g_Ra[(b*2+0)*NPIX+p]=r0/ssum;
        g_Ra[(b*2+1)*NPIX+p]=r1/ssum;
    }
}

// cluster moments + bin index + global hist -> inverses + gcdf
__global__ void kClusterBin(){
    int b = blockIdx.y;
    __shared__ float sh[64];
    if(threadIdx.x<64) sh[threadIdx.x]=0.f;
    __syncthreads();
    float mn = u2f(g_mm[b][0]), mx = u2f(g_mm[b][1]);
    float inv_rng = 1.f/(mx-mn+1e-8f);
    double a[20];
    for(int i=0;i<20;i++) a[i]=0.0;
    int per = NPIX/64;
    int lo = blockIdx.x*per, hi = lo+per;
    for(int p=lo+threadIdx.x;p<hi;p+=blockDim.x){
        float w0=g_Ra[(b*2+0)*NPIX+p], w1=g_Ra[(b*2+1)*NPIX+p];
        float lpv=g_Lp[b*NPIX+p];
        double x0=lpv, x1=g_E[b*NPIX+p], x2=g_S[b*NPIX+p];
        a[0]+=w0; a[1]+=w0*x0; a[2]+=w0*x1; a[3]+=w0*x2;
        a[4]+=w0*x0*x0; a[5]+=w0*x0*x1; a[6]+=w0*x0*x2;
        a[7]+=w0*x1*x1; a[8]+=w0*x1*x2; a[9]+=w0*x2*x2;
        a[10]+=w1; a[11]+=w1*x0; a[12]+=w1*x1; a[13]+=w1*x2;
        a[14]+=w1*x0*x0; a[15]+=w1*x0*x1; a[16]+=w1*x0*x2;
        a[17]+=w1*x1*x1; a[18]+=w1*x1*x2; a[19]+=w1*x2*x2;
        float ln = (lpv-mn)*inv_rng;
        ln = fminf(fmaxf(ln,0.f),1.f);
        int c = (int)(ln*32.f); c = c<0?0:(c>31?31:c);
        g_idxb[b*NPIX+p] = (unsigned char)c;
        atomicAdd(&sh[c],    w0);
        atomicAdd(&sh[32+c], w1);
    }
    for(int m=0;m<20;m++){
        double r=blockReduceD(a[m]);
        if(threadIdx.x==0) atomicAdd(&g_clacc[b][m/10][m%10],r);
    }
    __syncthreads();
    if(threadIdx.x<64 && sh[threadIdx.x]!=0.f)
        atomicAdd(&g_ghist[b][threadIdx.x>>5][threadIdx.x&31],(double)sh[threadIdx.x]);
    gridBarrier(64*BB);
    if(blockIdx.x==0 && blockIdx.y==0 && threadIdx.x<4){
        int t = threadIdx.x;
        int bb=t>>1, k=t&1;
        double A[10];
        for(int i=0;i<10;i++) A[i]=vloadd(&g_clacc[bb][k][i]);
        double Ws = A[0] + 1e-8;
        double mu[3] = {A[1]/Ws, A[2]/Ws, A[3]/Ws};
        double Sx[3] = {A[1], A[2], A[3]};
        double Sxx[9] = {A[4],A[5],A[6], A[5],A[7],A[8], A[6],A[8],A[9]};
        double C[9];
        for(int i=0;i<3;i++) for(int j2=0;j2<3;j2++)
            C[i*3+j2] = (Sxx[i*3+j2] - mu[i]*Sx[j2] - mu[j2]*Sx[i] + A[0]*mu[i]*mu[j2])/Ws + ((i==j2)?1e-6:0.0);
        double I[9]; inv3(C, I);
        for(int i=0;i<9;i++) g_clinv[bb][k][i]=I[i];
        for(int i=0;i<3;i++) g_clmu[bb][k][i]=mu[i];
        for(int i=0;i<10;i++) g_clacc[bb][k][i]=0.0;
        double tot=0; for(int c=0;c<32;c++) tot += vloadd(&g_ghist[bb][k][c]);
        double cum=0;
        for(int c=0;c<32;c++){ cum += vloadd(&g_ghist[bb][k][c])/(tot+1e-8); g_gcdf[bb][k][c]=(float)cum; g_ghist[bb][k][c]=0.0; }
        if(k==0){ g_mm[bb][0]=0xFFFFFFFFu; g_mm[bb][1]=0u; }
    }
}

// DM (k==0 threads) fused with horizontal box pass
__global__ void kDMBoxH(){
    int bk = blockIdx.y; int b=bk>>1, k=bk&1;
    int p = blockIdx.x*blockDim.x + threadIdx.x;
    int y = p / WW, x = p % WW;
    float s0=0.f,s1=0.f,s2=0.f;
    int lo = max(x-7,0), hi = min(x+7,WW-1);
    for(int xx=lo;xx<=hi;xx++){
        float r = g_Ra[bk*NPIX + y*WW + xx];
        float l = g_Lp[b*NPIX + y*WW + xx];
        s0+=r; s1+=r*l; s2+=r*l*l;
    }
    g_t0[bk*NPIX+p]=s0; g_t1[bk*NPIX+p]=s1; g_t2[bk*NPIX+p]=s2;
    if(k==0){
        int idx = b*NPIX + p;
        float X0=g_Lp[idx], X1=g_E[idx], X2=g_S[idx];
        float ra0=g_Ra[(b*2+0)*NPIX+p], ra1=g_Ra[(b*2+1)*NPIX+p];
        float ssum = ra0+ra1+2e-8f;
        float DM=0.f;
        for(int kk=0;kk<2;kk++){
            float xm0=X0-(float)g_clmu[b][kk][0];
            float xm1=X1-(float)g_clmu[b][kk][1];
            float xm2=X2-(float)g_clmu[b][kk][2];
            const double* I=g_clinv[b][kk];
            float q = xm0*xm0*(float)I[0] + xm1*xm1*(float)I[4] + xm2*xm2*(float)I[8]
                    + 2.f*xm0*xm1*(float)I[1] + 2.f*xm0*xm2*(float)I[2] + 2.f*xm1*xm2*(float)I[5];
            float Dk = sqrtf(q + 1e-8f);
            float Rt = ((kk==0?ra0:ra1)+1e-8f)/ssum;
            DM += Rt*Dk;
        }
        g_DM[idx]=DM;
    }
}

__global__ void kBoxV(){
    int bk = blockIdx.y; int b=bk>>1;
    int p = blockIdx.x*blockDim.x + threadIdx.x;
    int y = p / WW, x = p % WW;
    float s0=0.f,s1=0.f,s2=0.f;
    int lo = max(y-7,0), hi = min(y+7,HH-1);
    for(int yy=lo;yy<=hi;yy++){
        s0+=g_t0[bk*NPIX+yy*WW+x]; s1+=g_t1[bk*NPIX+yy*WW+x]; s2+=g_t2[bk*NPIX+yy*WW+x];
    }
    float cy = (float)(min(y+8,HH)-max(y-7,0));
    float cx = (float)(min(x+8,WW)-max(x-7,0));
    float c = cy*cx;
    float a0=s0/c, a1=s1/c, a2=s2/c;
    float den = a0 + 1e-8f;
    float mu = a1/den;
    float vb = fmaxf(a2/den - mu*mu, 1e-8f);
    g_lla[bk*NPIX+p] = fabsf(g_Lp[b*NPIX+p]-mu)/(sqrtf(vb)+1e-8f);
    g_den[bk*NPIX+p] = a0;
}

// fused GLD: tiled column histograms in shared (bin-prefix form), vertical+horizontal sliding
__global__ void __launch_bounds__(128,8) kGLDTile(){
    int bk = blockIdx.z; int b=bk>>1, k=bk&1;
    int strip = blockIdx.x;            // 8 strips of 48 cols
    int y0 = blockIdx.y*GTY;           // 16 segs of 24 rows
    int warp = threadIdx.x>>5, lane = threadIdx.x&31;
    __shared__ float ch[62][32];
    const float* rk = g_Ra + bk*NPIX;
    const unsigned char* bi = g_idxb + b*NPIX;
    int xbase = strip*48 - 7;
    for(int i=threadIdx.x;i<62*32;i+=128) ((float*)ch)[i]=0.f;
    __syncthreads();
    for(int c=warp;c<62;c+=4){
        int x = xbase+c;
        if(x<0||x>=WW) continue;
        float P=0.f;
        for(int r=y0-7;r<=y0+6;r++){
            if(r<0||r>=HH) continue;
            float v=rk[r*WW+x]; int bn=bi[r*WW+x];
            if(lane>=bn) P+=v;
        }
        ch[c][lane]=P;
    }
    float gc = g_gcdf[b][k][lane];
    __syncthreads();
    for(int y=y0;y<y0+GTY;y++){
        int ra=y+7;
        if(ra<HH){
            for(int c=warp;c<62;c+=4){
                int x=xbase+c; if(x<0||x>=WW) continue;
                float v=rk[ra*WW+x]; int bn=bi[ra*WW+x];
                if(lane>=bn) ch[c][lane]+=v;
            }
        }
        __syncthreads();
        {
            int xo0 = warp*12;
            float S=0.f;
            #pragma unroll
            for(int c=0;c<14;c++) S += ch[xo0+c][lane];
            float cy = (float)(min(y+8,HH)-max(y-7,0));
            for(int j=0;j<12;j++){
                int xo = xo0+j;
                S += ch[xo+14][lane];
                int x = strip*48 + xo;
                float cx = (float)(min(x+8,WW)-max(x-7,0));
                float den = g_den[bk*NPIX + y*WW+x] + 1e-8f;
                float diff = fabsf(S/(cy*cx)/den - gc);
                for(int o=16;o;o>>=1) diff += __shfl_down_sync(0xffffffffu,diff,o);
                if(lane==0) g_gld[bk*NPIX + y*WW+x] = diff*(1.f/32.f);
                S -= ch[xo][lane];
            }
        }
        __syncthreads();
        int rs=y-7;
        if(rs>=0){
            for(int c=warp;c<62;c+=4){
                int x=xbase+c; if(x<0||x>=WW) continue;
                float v=rk[rs*WW+x]; int bn=bi[rs*WW+x];
                if(lane>=bn) ch[c][lane]-=v;
            }
        }
        __syncthreads();
    }
}

// final phase: gamma/La inline, cooperative 1%/99% selects, final normalize
__global__ void __launch_bounds__(1024,1) kFinalPhase(float* __restrict__ out){
    int nbTot = 4*SELG;   // 64
    int job = blockIdx.x/SELG, chunk = blockIdx.x%SELG;
    int per = BN/64;
    int lo = blockIdx.x*per;
    for(int idx=lo+threadIdx.x; idx<lo+per; idx+=blockDim.x){
        int b = idx / NPIX, p = idx % NPIX;
        float gamma = 1.f;
        for(int k=0;k<2;k++){
            int s = b*2+k;
            float zl = (g_lla[s*NPIX+p]-g_sv[20+s])/(g_sv[24+s]*1.4826f+1e-8f);
            float zg = (g_gld[s*NPIX+p]-g_sv[28+s])/(g_sv[32+s]*1.4826f+1e-8f);
            gamma += g_Ra[s*NPIX+p]*(0.5f*softplusf(zl)+0.5f*softplusf(zg));
        }
        float mdE=g_sv[b*3+1], mdS=g_sv[b*3+2];
        float sdE=g_sv[6+b*3+1]*1.4826f+1e-8f, sdS=g_sv[6+b*3+2]*1.4826f+1e-8f;
        float dE=(g_E[idx]-mdE)/sdE-(float)g_esinv[b][3];
        float dS=(g_S[idx]-mdS)/sdS-(float)g_esinv[b][4];
        float d2 = dE*dE*(float)g_esinv[b][0] + 2.f*dE*dS*(float)g_esinv[b][1] + dS*dS*(float)g_esinv[b][2];
        float Rs = expf(-0.5f*d2);
        g_La[idx] = fmaxf(g_DM[idx]*gamma*(1.f-Rs), 0.f);
    }
    coopZero(4, nbTot);
    gridBarrier(nbTot);
    const int* jb = &g_seljobs[(18+job)*6];
    const float4* src = (const float4*)selSrc(jb[1], jb[2]);
    float v0 = coopSel(src,0.f,0,(unsigned)jb[3],job,0,chunk,nbTot);
    if(chunk==0&&threadIdx.x==0) g_sv[jb[4]]=v0;
    float v1 = coopSel(src,0.f,0,(unsigned)jb[3]+1u,job,3,chunk,nbTot);
    if(chunk==0&&threadIdx.x==0) g_sv[jb[5]]=v1;
    gridBarrier(nbTot);
    for(int idx=lo+threadIdx.x; idx<lo+per; idx+=blockDim.x){
        int b = idx / NPIX;
        float q1 = vloadf(&g_sv[36+4*b]) + 0.55f*(vloadf(&g_sv[37+4*b])-vloadf(&g_sv[36+4*b]));
        float q9 = vloadf(&g_sv[38+4*b]) + 0.45f*(vloadf(&g_sv[39+4*b])-vloadf(&g_sv[38+4*b]));
        float v = (g_La[idx]-q1)/(q9-q1+1e-8f);
        out[BN + idx] = fminf(fmaxf(v,0.f),1.f);   // output #2
    }
}

// ======================= host =======================
extern "C" void kernel_launch(void* const* d_in, const int* in_sizes, int n_in,
                              void* d_out, int out_size){
    const float* lab   = (const float*)d_in[0];
    const float* arand = (const float*)d_in[1];
    float* out = (float*)d_out;
    const int EB = (BN+255)/256;      // 1152 (exact)

    kSobelE<<<dim3(24,24,BB),256>>>(lab);
    kSolve<<<1,32>>>();
    kLperp<<<EB,256>>>(lab,out);

    selCoop<<<6*SELG,1024>>>(0,6);        // med+MAD of Lp,E,S
    kCovEighCdir<<<64,256>>>(arand);
    kKurtAcc<<<dim3(64,BB),256>>>();
    kKurtPick<<<1,32>>>();

    kPhaseZ<<<4*SELG,1024>>>();           // zb + quartile brackets
    kEM<<<EMB,1024>>>();                  // persistent EM -> Ra

    kClusterBin<<<dim3(64,BB),256>>>();
    kDMBoxH<<<dim3(576,4),256>>>();
    kBoxV<<<dim3(576,4),256>>>();
    kGLDTile<<<dim3(8,16,4),128>>>();

    selCoop<<<8*SELG,1024>>>(10,8);       // LLA + GLD med+MAD (merged)

    kFinalPhase<<<4*SELG,1024>>>(out);    // gamma/La + quantiles + normalize
}

// round 8
// speedup vs baseline: 1.5177x; 1.0001x over previous
#include <cuda_runtime.h>
#include <math.h>

#define HH 384
#define WW 384
#define NPIX (HH*WW)          // 147456
#define BB 2
#define BN (BB*NPIX)          // 294912
#define NDIR 128
#define EMB 32
#define SELG 16
#define GTY 24

// ======================= scratch buffers =======================
__device__ float g_E[BN];
__device__ float g_S[BN];
__device__ float g_Lp[BN];
__device__ float g_zb[BN];
__device__ float g_Ra[2*BN];     // [(b*2+k)*NPIX+n]
__device__ float g_DM[BN];
__device__ float g_t0[2*BN], g_t1[2*BN], g_t2[2*BN];
__device__ float g_lla[2*BN];
__device__ float g_den[2*BN];
__device__ float g_gld[2*BN];
__device__ float g_La[BN];
__device__ unsigned char g_idxb[BN];
__device__ unsigned g_jh[8*6*2048];     // cooperative select histograms

// ======================= small state =======================
__device__ float    g_sv[64];
__device__ unsigned g_mm[BB][2] = {{0xFFFFFFFFu,0u},{0xFFFFFFFFu,0u}};
__device__ double   g_reg[BB][5];
__device__ double   g_beta[BB][2];
__device__ double   g_cacc[BB][9];
__device__ double   g_mean3[BB][3];
__device__ double   g_wwh[BB][9];
__device__ float    g_cdir[BB*NDIR*3];
__device__ float    g_cbest[BB][3];
__device__ double   g_dirm[BB][NDIR][4];
__device__ double   g_emacc2[9][BB][6];
__device__ double   g_clacc[BB][2][10];
__device__ double   g_clmu[BB][2][3];
__device__ double   g_clinv[BB][2][9];
__device__ double   g_ghist[BB][2][32];
__device__ float    g_gcdf[BB][2][32];
__device__ double   g_esinv[BB][6];

// grid-wide barrier (monotonic generation; arrive self-resets)
__device__ int g_barArrive = 0;
__device__ int g_barGen = 0;

static __device__ __forceinline__ void gridBarrier(int nb){
    __threadfence();
    __syncthreads();
    if(threadIdx.x==0){
        int gen = *(volatile int*)&g_barGen;
        if(atomicAdd(&g_barArrive,1)==nb-1){
            g_barArrive = 0;
            __threadfence();
            *(volatile int*)&g_barGen = gen+1;
        } else {
            while(*(volatile int*)&g_barGen == gen) { }
        }
    }
    __syncthreads();
}

static __device__ __forceinline__ double vloadd(const double* p){ return *(volatile const double*)p; }
static __device__ __forceinline__ float  vloadf(const float* p){ return *(volatile const float*)p; }

// ======================= helpers =======================
static __device__ __forceinline__ unsigned f2u(float f){
    unsigned u = __float_as_uint(f);
    return (u & 0x80000000u) ? ~u : (u | 0x80000000u);
}
static __device__ __forceinline__ float u2f(unsigned u){
    unsigned v = (u & 0x80000000u) ? (u & 0x7FFFFFFFu) : ~u;
    return __uint_as_float(v);
}
static __device__ __forceinline__ float softplusf(float x){
    float t = log1pf(expf(-fabsf(x)));
    return x >= 0.f ? x + t : t;
}
static __device__ double blockReduceD(double v){
    __shared__ double sh[32];
    int lane = threadIdx.x & 31, wid = threadIdx.x >> 5;
    for (int o=16;o;o>>=1) v += __shfl_down_sync(0xffffffffu, v, o);
    if (lane==0) sh[wid] = v;
    __syncthreads();
    int nw = (blockDim.x + 31) >> 5;
    v = (threadIdx.x < nw) ? sh[threadIdx.x] : 0.0;
    if (wid==0) for (int o=16;o;o>>=1) v += __shfl_down_sync(0xffffffffu, v, o);
    __syncthreads();
    return v;
}
static __device__ void eigh3(const double* A, double* e, double* V){
    double a[9]; for(int i=0;i<9;i++) a[i]=A[i];
    for(int i=0;i<9;i++) V[i] = (i%4==0)?1.0:0.0;
    for(int sweep=0;sweep<40;sweep++){
        double off = fabs(a[1])+fabs(a[2])+fabs(a[5]);
        if(off < 1e-300) break;
        for(int p=0;p<2;p++) for(int q=p+1;q<3;q++){
            double apq=a[p*3+q];
            if(fabs(apq) < 1e-300) continue;
            double app=a[p*3+p], aqq=a[q*3+q];
            double th=(aqq-app)/(2.0*apq);
            double t=(th>=0?1.0:-1.0)/(fabs(th)+sqrt(th*th+1.0));
            double c=1.0/sqrt(t*t+1.0), s=t*c;
            for(int i=0;i<3;i++){ double x=a[i*3+p],y=a[i*3+q]; a[i*3+p]=c*x-s*y; a[i*3+q]=s*x+c*y; }
            for(int i=0;i<3;i++){ double x=a[p*3+i],y=a[q*3+i]; a[p*3+i]=c*x-s*y; a[q*3+i]=s*x+c*y; }
            for(int i=0;i<3;i++){ double x=V[i*3+p],y=V[i*3+q]; V[i*3+p]=c*x-s*y; V[i*3+q]=s*x+c*y; }
        }
    }
    e[0]=a[0]; e[1]=a[4]; e[2]=a[8];
}
static __device__ void inv3(const double* m, double* inv){
    double a=m[0],b=m[1],c=m[2],d=m[3],e=m[4],f=m[5],g=m[6],h=m[7],i=m[8];
    double A=e*i-f*h, B=c*h-b*i, C=b*f-c*e;
    double D=f*g-d*i, E=a*i-c*g, F=c*d-a*f;
    double G=d*h-e*g, Hh=b*g-a*h, I=a*e-b*d;
    double det=a*A+b*D+c*G, id=1.0/det;
    inv[0]=A*id; inv[1]=B*id; inv[2]=C*id;
    inv[3]=D*id; inv[4]=E*id; inv[5]=F*id;
    inv[6]=G*id; inv[7]=Hh*id; inv[8]=I*id;
}

// ======================= cooperative radix select =======================
// jobs: {kind, type, b, rank, slotA, slotB}
__device__ const int g_seljobs[22*6] = {
 0,0,0,73727,0,6,   0,1,0,73727,1,7,   0,2,0,73727,2,8,
 0,0,1,73727,3,9,   0,1,1,73727,4,10,  0,2,1,73727,5,11,
 1,3,0,36863,12,13,  1,3,0,110591,14,15,  1,3,1,36863,16,17,  1,3,1,110591,18,19,
 0,4,0,73727,20,24,  0,5,0,73727,21,25,  0,4,1,73727,22,26,  0,5,1,73727,23,27,
 0,6,0,73727,28,32,  0,7,0,73727,29,33,  0,6,1,73727,30,34,  0,7,1,73727,31,35,
 1,8,0,1474,36,37,  1,8,0,145980,38,39,  1,8,1,1474,40,41,  1,8,1,145980,42,43
};

static __device__ const float* selSrc(int type, int b){
    switch(type){
        case 0: return g_Lp + b*NPIX;
        case 1: return g_E  + b*NPIX;
        case 2: return g_S  + b*NPIX;
        case 3: return g_zb + b*NPIX;
        case 4: return g_lla + (b*2+0)*NPIX;
        case 5: return g_lla + (b*2+1)*NPIX;
        case 6: return g_gld + (b*2+0)*NPIX;
        case 7: return g_gld + (b*2+1)*NPIX;
        default: return g_La + b*NPIX;
    }
}

static __device__ void coopZero(int njobs, int nbTot){
    int total = njobs*6*2048;
    for(int i=blockIdx.x*blockDim.x+threadIdx.x; i<total; i+=nbTot*blockDim.x)
        g_jh[i]=0u;
}

// 3-pass (11/11/10 bit) cooperative select across SELG blocks per job.
static __device__ float coopSel(const float4* __restrict__ src4, float ref, int useAbs, unsigned rank,
                                int jobLocal, int passBase, int chunk, int nbTot){
    __shared__ unsigned sh[2048];
    __shared__ unsigned sres[2];
    unsigned pref=0, rk=rank;
    for(int pass=0; pass<3; pass++){
        unsigned* hist = g_jh + (jobLocal*6+passBase+pass)*2048;
        int nbin = (pass==2)?1024:2048;
        for(int i=threadIdx.x;i<nbin;i+=blockDim.x) sh[i]=0u;
        __syncthreads();
        int per = (NPIX/4)/SELG;      // 2304
        int lo = chunk*per;
        for(int i=lo+threadIdx.x;i<lo+per;i+=blockDim.x){
            float4 v4 = src4[i];
            float vv[4]={v4.x,v4.y,v4.z,v4.w};
            #pragma unroll
            for(int c=0;c<4;c++){
                float v=vv[c]; if(useAbs) v=fabsf(v-ref);
                unsigned key=f2u(v);
                if(pass==0) atomicAdd(&sh[key>>21],1u);
                else if(pass==1){ if((key>>21)==(pref>>21)) atomicAdd(&sh[(key>>10)&2047u],1u); }
                else { if((key>>10)==(pref>>10)) atomicAdd(&sh[key&1023u],1u); }
            }
        }
        __syncthreads();
        for(int i=threadIdx.x;i<nbin;i+=blockDim.x) if(sh[i]) atomicAdd(&hist[i],sh[i]);
        gridBarrier(nbTot);
        if(threadIdx.x<32){
            int lane=threadIdx.x, perl=nbin>>5;
            unsigned s=0;
            for(int i=0;i<perl;i++) s+=hist[lane*perl+i];
            unsigned cum=s;
            #pragma unroll
            for(int o=1;o<32;o<<=1){ unsigned t=__shfl_up_sync(0xffffffffu,cum,o); if(lane>=o) cum+=t; }
            unsigned prev=cum-s;
            if(prev<=rk && rk<cum){
                unsigned rr=rk-prev; int bin=lane*perl;
                for(int i=0;i<perl;i++){ unsigned c=hist[lane*perl+i]; if(rr<c){ bin=lane*perl+i; break;} rr-=c; }
                sres[0]=(pass==0)? ((unsigned)bin<<21) : (pass==1)? (pref|((unsigned)bin<<10)) : (pref|(unsigned)bin);
                sres[1]=rr;
            }
        }
        __syncthreads();
        pref=sres[0]; rk=sres[1];
        __syncthreads();
    }
    return u2f(pref);
}

__global__ void __launch_bounds__(1024,1) selCoop(int jobBase, int njobs){
    int nbTot = njobs*SELG;
    int job = blockIdx.x/SELG, chunk = blockIdx.x%SELG;
    coopZero(njobs, nbTot);
    gridBarrier(nbTot);
    const int* jb = &g_seljobs[(jobBase+job)*6];
    const float4* src = (const float4*)selSrc(jb[1], jb[2]);
    if(jb[0]==0){
        float med = coopSel(src,0.f,0,(unsigned)jb[3],job,0,chunk,nbTot);
        if(chunk==0&&threadIdx.x==0) g_sv[jb[4]]=med;
        float mad = coopSel(src,med,1,(unsigned)jb[3],job,3,chunk,nbTot);
        if(chunk==0&&threadIdx.x==0) g_sv[jb[5]]=mad;
    } else {
        float v0 = coopSel(src,0.f,0,(unsigned)jb[3],job,0,chunk,nbTot);
        if(chunk==0&&threadIdx.x==0) g_sv[jb[4]]=v0;
        float v1 = coopSel(src,0.f,0,(unsigned)jb[3]+1u,job,3,chunk,nbTot);
        if(chunk==0&&threadIdx.x==0) g_sv[jb[5]]=v1;
    }
}

// ======================= pipeline kernels =======================
// fused Sobel + avg3 + regression accumulation, tiled in shared memory
__global__ void __launch_bounds__(256) kSobelE(const float* __restrict__ lab){
    __shared__ float sL[20][20];
    __shared__ float sP[18][18];
    int b = blockIdx.z;
    int x0 = blockIdx.x*16, y0 = blockIdx.y*16;
    int tid = threadIdx.x;
    int tx = tid & 15, ty = tid >> 4;
    const float* L = lab + (size_t)b*3*NPIX;
    for(int i=tid;i<400;i+=256){
        int jj=i/20, ii=i%20;
        int yy=y0-2+jj, xx=x0-2+ii;
        sL[jj][ii] = (yy>=0&&yy<HH&&xx>=0&&xx<WW) ? L[yy*WW+xx] : 0.f;
    }
    __syncthreads();
    for(int i=tid;i<324;i+=256){
        int jj=i/18, ii=i%18;
        int py=y0-1+jj, px=x0-1+ii;
        float v=0.f;
        if(py>=0&&py<HH&&px>=0&&px<WW){
            float l00=sL[jj][ii],   l01=sL[jj][ii+1],   l02=sL[jj][ii+2];
            float l10=sL[jj+1][ii],                     l12=sL[jj+1][ii+2];
            float l20=sL[jj+2][ii], l21=sL[jj+2][ii+1], l22=sL[jj+2][ii+2];
            float gx = -l00 + l02 - 2.f*l10 + 2.f*l12 - l20 + l22;
            float gy = -l00 - 2.f*l01 - l02 + l20 + 2.f*l21 + l22;
            v = gx*gx + gy*gy;
        }
        sP[jj][ii]=v;
    }
    __syncthreads();
    int y=y0+ty, x=x0+tx;
    int p = y*WW+x, idx = b*NPIX+p;
    float s = sP[ty][tx]  +sP[ty][tx+1]  +sP[ty][tx+2]
            + sP[ty+1][tx]+sP[ty+1][tx+1]+sP[ty+1][tx+2]
            + sP[ty+2][tx]+sP[ty+2][tx+1]+sP[ty+2][tx+2];
    float E = s/9.f;
    float av = L[NPIX+p], bv = L[2*NPIX+p];
    float S = sqrtf(av*av+bv*bv+1e-8f);
    g_E[idx]=E; g_S[idx]=S;
    double e=E, sv=S, l=L[p];
    double r;
    r=blockReduceD(e*e);  if(tid==0) atomicAdd(&g_reg[b][0],r);
    r=blockReduceD(e*sv); if(tid==0) atomicAdd(&g_reg[b][1],r);
    r=blockReduceD(sv*sv);if(tid==0) atomicAdd(&g_reg[b][2],r);
    r=blockReduceD(e*l);  if(tid==0) atomicAdd(&g_reg[b][3],r);
    r=blockReduceD(sv*l); if(tid==0) atomicAdd(&g_reg[b][4],r);
}

__global__ void kSolve(){
    int b = threadIdx.x; if(b>=BB) return;
    double ee=g_reg[b][0]+1e-6, es=g_reg[b][1], ss=g_reg[b][2]+1e-6;
    double el=g_reg[b][3], sl=g_reg[b][4];
    double det = ee*ss - es*es;
    g_beta[b][0] = (ss*el - es*sl)/det;
    g_beta[b][1] = (ee*sl - es*el)/det;
    for(int i=0;i<5;i++) g_reg[b][i]=0.0;
}

__global__ void kLperp(const float* __restrict__ lab, float* __restrict__ out){
    int idx = blockIdx.x*blockDim.x + threadIdx.x;
    int b = idx / NPIX, p = idx % NPIX;
    float v = lab[(size_t)b*3*NPIX+p] - (float)g_beta[b][0]*g_E[idx] - (float)g_beta[b][1]*g_S[idx];
    g_Lp[idx] = v;
    out[idx] = v;   // output #1
    unsigned k = f2u(v);
    __shared__ unsigned smn[256], smx[256];
    smn[threadIdx.x]=k; smx[threadIdx.x]=k;
    __syncthreads();
    for(int o=128;o>0;o>>=1){
        if(threadIdx.x<o){ smn[threadIdx.x]=min(smn[threadIdx.x],smn[threadIdx.x+o]);
                           smx[threadIdx.x]=max(smx[threadIdx.x],smx[threadIdx.x+o]); }
        __syncthreads();
    }
    if(threadIdx.x==0){ atomicMin(&g_mm[b][0],smn[0]); atomicMax(&g_mm[b][1],smx[0]); }
}

// robust-z cov + eigh + whitening + ES inverse + whitened directions
__global__ void kCovEighCdir(const float* __restrict__ arand){
    int b = blockIdx.x >> 5, chunk = blockIdx.x & 31;
    float md[3], sd[3];
    for(int f=0;f<3;f++){ md[f]=g_sv[b*3+f]; sd[f]=g_sv[6+b*3+f]*1.4826f+1e-8f; }
    double a[9]={0,0,0,0,0,0,0,0,0};
    int per = NPIX/32;
    int lo = chunk*per, hi = lo+per;
    for(int p=lo+threadIdx.x;p<hi;p+=blockDim.x){
        float z0=(g_Lp[b*NPIX+p]-md[0])/sd[0];
        float z1=(g_E [b*NPIX+p]-md[1])/sd[1];
        float z2=(g_S [b*NPIX+p]-md[2])/sd[2];
        a[0]+=z0; a[1]+=z1; a[2]+=z2;
        a[3]+=(double)z0*z0; a[4]+=(double)z0*z1; a[5]+=(double)z0*z2;
        a[6]+=(double)z1*z1; a[7]+=(double)z1*z2; a[8]+=(double)z2*z2;
    }
    for(int m=0;m<9;m++){ double r=blockReduceD(a[m]); if(threadIdx.x==0) atomicAdd(&g_cacc[b][m],r); }
    gridBarrier(64);
    if(blockIdx.x==0){
        int t = threadIdx.x;
        if(t<BB){
            int bb = t;
            double N = (double)NPIX;
            double mu[3]; for(int i=0;i<3;i++){ mu[i]=vloadd(&g_cacc[bb][i])/N; g_mean3[bb][i]=mu[i]; }
            double C[9];
            C[0]=vloadd(&g_cacc[bb][3])/N-mu[0]*mu[0]; C[1]=vloadd(&g_cacc[bb][4])/N-mu[0]*mu[1]; C[2]=vloadd(&g_cacc[bb][5])/N-mu[0]*mu[2];
            C[4]=vloadd(&g_cacc[bb][6])/N-mu[1]*mu[1]; C[5]=vloadd(&g_cacc[bb][7])/N-mu[1]*mu[2]; C[8]=vloadd(&g_cacc[bb][8])/N-mu[2]*mu[2];
            C[3]=C[1]; C[6]=C[2]; C[7]=C[5];
            {
                double c00=C[4]+1e-6, c01=C[5], c11=C[8]+1e-6;
                double det=c00*c11-c01*c01;
                g_esinv[bb][0]=c11/det; g_esinv[bb][1]=-c01/det; g_esinv[bb][2]=c00/det;
                g_esinv[bb][3]=mu[1]; g_esinv[bb][4]=mu[2];
            }
            for(int i=0;i<9;i++) C[i] = C[i] > 1e-8 ? C[i] : 1e-8;
            double e[3], V[9];
            eigh3(C, e, V);
            for(int i=0;i<3;i++) for(int j=0;j<3;j++){
                double ssum=0; for(int k2=0;k2<3;k2++) ssum += V[i*3+k2]*(1.0/sqrt(e[k2]))*V[j*3+k2];
                g_wwh[bb][i*3+j]=ssum;
            }
            for(int i=0;i<9;i++) g_cacc[bb][i]=0.0;
        }
        __syncthreads();
        if(t < BB*NDIR){
            int bb = t / NDIR, d = t % NDIR;
            float a0=arand[(bb*NDIR+d)*3+0], a1=arand[(bb*NDIR+d)*3+1], a2=arand[(bb*NDIR+d)*3+2];
            float nr = sqrtf(a0*a0+a1*a1+a2*a2) + 1e-12f;
            double an[3]={a0/nr,a1/nr,a2/nr};
            for(int jj=0;jj<3;jj++){
                double ssum=0; for(int i=0;i<3;i++) ssum += g_wwh[bb][jj*3+i]*an[i];
                g_cdir[(bb*NDIR+d)*3+jj]=(float)ssum;
            }
        }
    }
}

// kurtosis moments: pixels in registers, all 128 dirs per block
__global__ void __launch_bounds__(256) kKurtAcc(){
    int b = blockIdx.y, chunk = blockIdx.x;
    __shared__ float scd[NDIR*3];
    __shared__ float sacc[NDIR*4];
    for(int i=threadIdx.x;i<NDIR*3;i+=256) scd[i]=g_cdir[b*NDIR*3+i];
    for(int i=threadIdx.x;i<NDIR*4;i+=256) sacc[i]=0.f;
    float md[3], sd[3], mn[3];
    for(int f=0;f<3;f++){ md[f]=g_sv[b*3+f]; sd[f]=g_sv[6+b*3+f]*1.4826f+1e-8f; mn[f]=(float)g_mean3[b][f]; }
    int base = b*NPIX + chunk*(NPIX/64);
    float d0[9], d1[9], d2[9];
    #pragma unroll
    for(int i=0;i<9;i++){
        int p = base + i*256 + threadIdx.x;
        d0[i]=(g_Lp[p]-md[0])/sd[0]-mn[0];
        d1[i]=(g_E [p]-md[1])/sd[1]-mn[1];
        d2[i]=(g_S [p]-md[2])/sd[2]-mn[2];
    }
    __syncthreads();
    int lane = threadIdx.x & 31;
    for(int d=0;d<NDIR;d++){
        float c0=scd[d*3], c1=scd[d*3+1], c2=scd[d*3+2];
        float s1=0,s2=0,s3=0,s4=0;
        #pragma unroll
        for(int i=0;i<9;i++){
            float z=d0[i]*c0+d1[i]*c1+d2[i]*c2;
            float z2=z*z;
            s1+=z; s2+=z2; s3+=z2*z; s4+=z2*z2;
        }
        for(int o=16;o;o>>=1){
            s1+=__shfl_down_sync(0xffffffffu,s1,o); s2+=__shfl_down_sync(0xffffffffu,s2,o);
            s3+=__shfl_down_sync(0xffffffffu,s3,o); s4+=__shfl_down_sync(0xffffffffu,s4,o);
        }
        if(lane==0){
            atomicAdd(&sacc[d*4+0],s1); atomicAdd(&sacc[d*4+1],s2);
            atomicAdd(&sacc[d*4+2],s3); atomicAdd(&sacc[d*4+3],s4);
        }
    }
    __syncthreads();
    for(int i=threadIdx.x;i<NDIR*4;i+=256)
        atomicAdd(&((double*)g_dirm)[b*NDIR*4+i], (double)sacc[i]);
}

__global__ void kKurtPick(){
    int b = threadIdx.x; if(b>=BB) return;
    double N=(double)NPIX, bestv=-1.0; int best=0;
    for(int d=0;d<NDIR;d++){
        double m1=g_dirm[b][d][0]/N, s2=g_dirm[b][d][1]/N, s3=g_dirm[b][d][2]/N, s4=g_dirm[b][d][3]/N;
        double m2=(s2-m1*m1)+1e-12;
        double m4=s4-4.0*m1*s3+6.0*m1*m1*s2-3.0*m1*m1*m1*m1;
        double kurt=fabs(m4/(m2*m2)-3.0);
        if(kurt>bestv){bestv=kurt;best=d;}
    }
    for(int j=0;j<3;j++) g_cbest[b][j]=g_cdir[(b*NDIR+best)*3+j];
    for(int d=0;d<NDIR;d++) for(int m=0;m<4;m++) g_dirm[b][d][m]=0.0;
}

// phase Z: compute zb inline, then cooperative quartile-bracket selects
__global__ void __launch_bounds__(1024,1) kPhaseZ(){
    int nbTot = 4*SELG;   // 64
    int job = blockIdx.x/SELG, chunk = blockIdx.x%SELG;
    int per = BN/64;      // 4608
    int lo = blockIdx.x*per;
    for(int idx=lo+threadIdx.x; idx<lo+per; idx+=blockDim.x){
        int b = idx / NPIX;
        float md0=g_sv[b*3+0], md1=g_sv[b*3+1], md2=g_sv[b*3+2];
        float sd0=g_sv[6+b*3+0]*1.4826f+1e-8f, sd1=g_sv[6+b*3+1]*1.4826f+1e-8f, sd2=g_sv[6+b*3+2]*1.4826f+1e-8f;
        float d0=(g_Lp[idx]-md0)/sd0-(float)g_mean3[b][0];
        float d1=(g_E [idx]-md1)/sd1-(float)g_mean3[b][1];
        float d2=(g_S [idx]-md2)/sd2-(float)g_mean3[b][2];
        g_zb[idx] = d0*g_cbest[b][0]+d1*g_cbest[b][1]+d2*g_cbest[b][2];
    }
    coopZero(4, nbTot);
    gridBarrier(nbTot);
    const int* jb = &g_seljobs[(6+job)*6];
    const float4* src = (const float4*)selSrc(jb[1], jb[2]);
    float v0 = coopSel(src,0.f,0,(unsigned)jb[3],job,0,chunk,nbTot);
    if(chunk==0&&threadIdx.x==0) g_sv[jb[4]]=v0;
    float v1 = coopSel(src,0.f,0,(unsigned)jb[3]+1u,job,3,chunk,nbTot);
    if(chunk==0&&threadIdx.x==0) g_sv[jb[5]]=v1;
}

// persistent EM: per-iteration accumulator slots (1 barrier/iter), zb in registers
__global__ void __launch_bounds__(1024,1) kEM(){
    int blk = blockIdx.x;
    int b = blk >> 4, sub = blk & 15;
    const float* zb = g_zb + b*NPIX;
    float x[9];
    int base = sub*(NPIX/16) + threadIdx.x;
    #pragma unroll
    for(int i=0;i<9;i++) x[i] = zb[base + i*1024];
    {
        double* acc = (double*)g_emacc2;
        int tot = 9*BB*6;
        for(int i=blk*blockDim.x+threadIdx.x; i<tot; i+=EMB*blockDim.x) acc[i]=0.0;
    }
    float q25 = g_sv[12+4*b] + 0.75f*(g_sv[13+4*b]-g_sv[12+4*b]);
    float q75 = g_sv[14+4*b] + 0.25f*(g_sv[15+4*b]-g_sv[14+4*b]);
    double mu0=q25, mu1=q75, var0=1.0, var1=1.0, pi0=0.5, pi1=0.5;
    gridBarrier(EMB);
    for(int it=0; it<9; it++){
        float m0=(float)mu0, m1=(float)mu1;
        float v0=(float)var0+1e-6f, v1=(float)var1+1e-6f;
        float lw0=-0.5f*logf(v0)+logf((float)pi0+1e-8f);
        float lw1=-0.5f*logf(v1)+logf((float)pi1+1e-8f);
        float iv0=0.5f/v0, iv1=0.5f/v1;
        float a0=0,a1=0,a2=0,a3=0,a4=0,a5=0;
        #pragma unroll
        for(int i=0;i<9;i++){
            float xx=x[i];
            float lp0=-(xx-m0)*(xx-m0)*iv0+lw0;
            float lp1=-(xx-m1)*(xx-m1)*iv1+lw1;
            float R0=1.f/(1.f+expf(lp1-lp0));
            float R1=1.f/(1.f+expf(lp0-lp1));
            a0+=R0; a1+=R0*xx; a2+=R0*xx*xx;
            a3+=R1; a4+=R1*xx; a5+=R1*xx*xx;
        }
        double s[6]={a0,a1,a2,a3,a4,a5};
        for(int m=0;m<6;m++){
            double r=blockReduceD(s[m]);
            if(threadIdx.x==0) atomicAdd(&g_emacc2[it][b][m],r);
        }
        gridBarrier(EMB);
        {
            double Sr0=vloadd(&g_emacc2[it][b][0]), Sx0=vloadd(&g_emacc2[it][b][1]), Sxx0=vloadd(&g_emacc2[it][b][2]);
            double Sr1=vloadd(&g_emacc2[it][b][3]), Sx1=vloadd(&g_emacc2[it][b][4]), Sxx1=vloadd(&g_emacc2[it][b][5]);
            double den0=Sr0+1e-8; mu0=Sx0/den0;
            var0=(Sxx0-2.0*mu0*Sx0+mu0*mu0*Sr0)/den0+1e-6; pi0=Sr0/(double)NPIX;
            double den1=Sr1+1e-8; mu1=Sx1/den1;
            var1=(Sxx1-2.0*mu1*Sx1+mu1*mu1*Sr1)/den1+1e-6; pi1=Sr1/(double)NPIX;
        }
    }
    float m0=(float)mu0, m1=(float)mu1;
    float v0=(float)var0+1e-6f, v1=(float)var1+1e-6f;
    float lw0=-0.5f*logf(v0)+logf((float)pi0+1e-8f);
    float lw1=-0.5f*logf(v1)+logf((float)pi1+1e-8f);
    float iv0=0.5f/v0, iv1=0.5f/v1;
    #pragma unroll
    for(int i=0;i<9;i++){
        float xx=x[i];
        float lp0=-(xx-m0)*(xx-m0)*iv0+lw0;
        float lp1=-(xx-m1)*(xx-m1)*iv1+lw1;
        float R0=1.f/(1.f+expf(lp1-lp0));
        float R1=1.f/(1.f+expf(lp0-lp1));
        float r0=powf(R0,0.9f), r1=powf(R1,0.9f);
        float ssum=r0+r1+1e-8f;
        int p = base + i*1024;
        g_Ra[(b*2+0)*NPIX+p]=r0/ssum;
        g_Ra[(b*2+1)*NPIX+p]=r1/ssum;
    }
}

// cluster moments + bin index + global hist -> inverses + gcdf
__global__ void kClusterBin(){
    int b = blockIdx.y;
    __shared__ float sh[64];
    if(threadIdx.x<64) sh[threadIdx.x]=0.f;
    __syncthreads();
    float mn = u2f(g_mm[b][0]), mx = u2f(g_mm[b][1]);
    float inv_rng = 1.f/(mx-mn+1e-8f);
    double a[20];
    for(int i=0;i<20;i++) a[i]=0.0;
    int per = NPIX/64;
    int lo = blockIdx.x*per, hi = lo+per;
    for(int p=lo+threadIdx.x;p<hi;p+=blockDim.x){
        float w0=g_Ra[(b*2+0)*NPIX+p], w1=g_Ra[(b*2+1)*NPIX+p];
        float lpv=g_Lp[b*NPIX+p];
        double x0=lpv, x1=g_E[b*NPIX+p], x2=g_S[b*NPIX+p];
        a[0]+=w0; a[1]+=w0*x0; a[2]+=w0*x1; a[3]+=w0*x2;
        a[4]+=w0*x0*x0; a[5]+=w0*x0*x1; a[6]+=w0*x0*x2;
        a[7]+=w0*x1*x1; a[8]+=w0*x1*x2; a[9]+=w0*x2*x2;
        a[10]+=w1; a[11]+=w1*x0; a[12]+=w1*x1; a[13]+=w1*x2;
        a[14]+=w1*x0*x0; a[15]+=w1*x0*x1; a[16]+=w1*x0*x2;
        a[17]+=w1*x1*x1; a[18]+=w1*x1*x2; a[19]+=w1*x2*x2;
        float ln = (lpv-mn)*inv_rng;
        ln = fminf(fmaxf(ln,0.f),1.f);
        int c = (int)(ln*32.f); c = c<0?0:(c>31?31:c);
        g_idxb[b*NPIX+p] = (unsigned char)c;
        atomicAdd(&sh[c],    w0);
        atomicAdd(&sh[32+c], w1);
    }
    for(int m=0;m<20;m++){
        double r=blockReduceD(a[m]);
        if(threadIdx.x==0) atomicAdd(&g_clacc[b][m/10][m%10],r);
    }
    __syncthreads();
    if(threadIdx.x<64 && sh[threadIdx.x]!=0.f)
        atomicAdd(&g_ghist[b][threadIdx.x>>5][threadIdx.x&31],(double)sh[threadIdx.x]);
    gridBarrier(64*BB);
    if(blockIdx.x==0 && blockIdx.y==0 && threadIdx.x<4){
        int t = threadIdx.x;
        int bb=t>>1, k=t&1;
        double A[10];
        for(int i=0;i<10;i++) A[i]=vloadd(&g_clacc[bb][k][i]);
        double Ws = A[0] + 1e-8;
        double mu[3] = {A[1]/Ws, A[2]/Ws, A[3]/Ws};
        double Sx[3] = {A[1], A[2], A[3]};
        double Sxx[9] = {A[4],A[5],A[6], A[5],A[7],A[8], A[6],A[8],A[9]};
        double C[9];
        for(int i=0;i<3;i++) for(int j2=0;j2<3;j2++)
            C[i*3+j2] = (Sxx[i*3+j2] - mu[i]*Sx[j2] - mu[j2]*Sx[i] + A[0]*mu[i]*mu[j2])/Ws + ((i==j2)?1e-6:0.0);
        double I[9]; inv3(C, I);
        for(int i=0;i<9;i++) g_clinv[bb][k][i]=I[i];
        for(int i=0;i<3;i++) g_clmu[bb][k][i]=mu[i];
        for(int i=0;i<10;i++) g_clacc[bb][k][i]=0.0;
        double tot=0; for(int c=0;c<32;c++) tot += vloadd(&g_ghist[bb][k][c]);
        double cum=0;
        for(int c=0;c<32;c++){ cum += vloadd(&g_ghist[bb][k][c])/(tot+1e-8); g_gcdf[bb][k][c]=(float)cum; g_ghist[bb][k][c]=0.0; }
        if(k==0){ g_mm[bb][0]=0xFFFFFFFFu; g_mm[bb][1]=0u; }
    }
}

// DM (k==0 threads) fused with horizontal box pass
__global__ void kDMBoxH(){
    int bk = blockIdx.y; int b=bk>>1, k=bk&1;
    int p = blockIdx.x*blockDim.x + threadIdx.x;
    int y = p / WW, x = p % WW;
    float s0=0.f,s1=0.f,s2=0.f;
    int lo = max(x-7,0), hi = min(x+7,WW-1);
    for(int xx=lo;xx<=hi;xx++){
        float r = g_Ra[bk*NPIX + y*WW + xx];
        float l = g_Lp[b*NPIX + y*WW + xx];
        s0+=r; s1+=r*l; s2+=r*l*l;
    }
    g_t0[bk*NPIX+p]=s0; g_t1[bk*NPIX+p]=s1; g_t2[bk*NPIX+p]=s2;
    if(k==0){
        int idx = b*NPIX + p;
        float X0=g_Lp[idx], X1=g_E[idx], X2=g_S[idx];
        float ra0=g_Ra[(b*2+0)*NPIX+p], ra1=g_Ra[(b*2+1)*NPIX+p];
        float ssum = ra0+ra1+2e-8f;
        float DM=0.f;
        for(int kk=0;kk<2;kk++){
            float xm0=X0-(float)g_clmu[b][kk][0];
            float xm1=X1-(float)g_clmu[b][kk][1];
            float xm2=X2-(float)g_clmu[b][kk][2];
            const double* I=g_clinv[b][kk];
            float q = xm0*xm0*(float)I[0] + xm1*xm1*(float)I[4] + xm2*xm2*(float)I[8]
                    + 2.f*xm0*xm1*(float)I[1] + 2.f*xm0*xm2*(float)I[2] + 2.f*xm1*xm2*(float)I[5];
            float Dk = sqrtf(q + 1e-8f);
            float Rt = ((kk==0?ra0:ra1)+1e-8f)/ssum;
            DM += Rt*Dk;
        }
        g_DM[idx]=DM;
    }
}

__global__ void kBoxV(){
    int bk = blockIdx.y; int b=bk>>1;
    int p = blockIdx.x*blockDim.x + threadIdx.x;
    int y = p / WW, x = p % WW;
    float s0=0.f,s1=0.f,s2=0.f;
    int lo = max(y-7,0), hi = min(y+7,HH-1);
    for(int yy=lo;yy<=hi;yy++){
        s0+=g_t0[bk*NPIX+yy*WW+x]; s1+=g_t1[bk*NPIX+yy*WW+x]; s2+=g_t2[bk*NPIX+yy*WW+x];
    }
    float cy = (float)(min(y+8,HH)-max(y-7,0));
    float cx = (float)(min(x+8,WW)-max(x-7,0));
    float c = cy*cx;
    float a0=s0/c, a1=s1/c, a2=s2/c;
    float den = a0 + 1e-8f;
    float mu = a1/den;
    float vb = fmaxf(a2/den - mu*mu, 1e-8f);
    g_lla[bk*NPIX+p] = fabsf(g_Lp[b*NPIX+p]-mu)/(sqrtf(vb)+1e-8f);
    g_den[bk*NPIX+p] = a0;
}

// fused GLD: tiled column histograms in shared (bin-prefix form), vertical+horizontal sliding
__global__ void __launch_bounds__(128,8) kGLDTile(){
    int bk = blockIdx.z; int b=bk>>1, k=bk&1;
    int strip = blockIdx.x;            // 8 strips of 48 cols
    int y0 = blockIdx.y*GTY;           // 16 segs of 24 rows
    int warp = threadIdx.x>>5, lane = threadIdx.x&31;
    __shared__ float ch[62][32];
    const float* rk = g_Ra + bk*NPIX;
    const unsigned char* bi = g_idxb + b*NPIX;
    int xbase = strip*48 - 7;
    for(int i=threadIdx.x;i<62*32;i+=128) ((float*)ch)[i]=0.f;
    __syncthreads();
    for(int c=warp;c<62;c+=4){
        int x = xbase+c;
        if(x<0||x>=WW) continue;
        float P=0.f;
        for(int r=y0-7;r<=y0+6;r++){
            if(r<0||r>=HH) continue;
            float v=rk[r*WW+x]; int bn=bi[r*WW+x];
            if(lane>=bn) P+=v;
        }
        ch[c][lane]=P;
    }
    float gc = g_gcdf[b][k][lane];
    __syncthreads();
    for(int y=y0;y<y0+GTY;y++){
        int ra=y+7;
        if(ra<HH){
            for(int c=warp;c<62;c+=4){
                int x=xbase+c; if(x<0||x>=WW) continue;
                float v=rk[ra*WW+x]; int bn=bi[ra*WW+x];
                if(lane>=bn) ch[c][lane]+=v;
            }
        }
        __syncthreads();
        {
            int xo0 = warp*12;
            float S=0.f;
            #pragma unroll
            for(int c=0;c<14;c++) S += ch[xo0+c][lane];
            float cy = (float)(min(y+8,HH)-max(y-7,0));
            for(int j=0;j<12;j++){
                int xo = xo0+j;
                S += ch[xo+14][lane];
                int x = strip*48 + xo;
                float cx = (float)(min(x+8,WW)-max(x-7,0));
                float den = g_den[bk*NPIX + y*WW+x] + 1e-8f;
                float diff = fabsf(S/(cy*cx)/den - gc);
                for(int o=16;o;o>>=1) diff += __shfl_down_sync(0xffffffffu,diff,o);
                if(lane==0) g_gld[bk*NPIX + y*WW+x] = diff*(1.f/32.f);
                S -= ch[xo][lane];
            }
        }
        __syncthreads();
        int rs=y-7;
        if(rs>=0){
            for(int c=warp;c<62;c+=4){
                int x=xbase+c; if(x<0||x>=WW) continue;
                float v=rk[rs*WW+x]; int bn=bi[rs*WW+x];
                if(lane>=bn) ch[c][lane]-=v;
            }
        }
        __syncthreads();
    }
}

// final phase: gamma/La inline, cooperative 1%/99% selects, final normalize
__global__ void __launch_bounds__(1024,1) kFinalPhase(float* __restrict__ out){
    int nbTot = 4*SELG;   // 64
    int job = blockIdx.x/SELG, chunk = blockIdx.x%SELG;
    int per = BN/64;
    int lo = blockIdx.x*per;
    for(int idx=lo+threadIdx.x; idx<lo+per; idx+=blockDim.x){
        int b = idx / NPIX, p = idx % NPIX;
        float gamma = 1.f;
        for(int k=0;k<2;k++){
            int s = b*2+k;
            float zl = (g_lla[s*NPIX+p]-g_sv[20+s])/(g_sv[24+s]*1.4826f+1e-8f);
            float zg = (g_gld[s*NPIX+p]-g_sv[28+s])/(g_sv[32+s]*1.4826f+1e-8f);
            gamma += g_Ra[s*NPIX+p]*(0.5f*softplusf(zl)+0.5f*softplusf(zg));
        }
        float mdE=g_sv[b*3+1], mdS=g_sv[b*3+2];
        float sdE=g_sv[6+b*3+1]*1.4826f+1e-8f, sdS=g_sv[6+b*3+2]*1.4826f+1e-8f;
        float dE=(g_E[idx]-mdE)/sdE-(float)g_esinv[b][3];
        float dS=(g_S[idx]-mdS)/sdS-(float)g_esinv[b][4];
        float d2 = dE*dE*(float)g_esinv[b][0] + 2.f*dE*dS*(float)g_esinv[b][1] + dS*dS*(float)g_esinv[b][2];
        float Rs = expf(-0.5f*d2);
        g_La[idx] = fmaxf(g_DM[idx]*gamma*(1.f-Rs), 0.f);
    }
    coopZero(4, nbTot);
    gridBarrier(nbTot);
    const int* jb = &g_seljobs[(18+job)*6];
    const float4* src = (const float4*)selSrc(jb[1], jb[2]);
    float v0 = coopSel(src,0.f,0,(unsigned)jb[3],job,0,chunk,nbTot);
    if(chunk==0&&threadIdx.x==0) g_sv[jb[4]]=v0;
    float v1 = coopSel(src,0.f,0,(unsigned)jb[3]+1u,job,3,chunk,nbTot);
    if(chunk==0&&threadIdx.x==0) g_sv[jb[5]]=v1;
    gridBarrier(nbTot);
    for(int idx=lo+threadIdx.x; idx<lo+per; idx+=blockDim.x){
        int b = idx / NPIX;
        float q1 = vloadf(&g_sv[36+4*b]) + 0.55f*(vloadf(&g_sv[37+4*b])-vloadf(&g_sv[36+4*b]));
        float q9 = vloadf(&g_sv[38+4*b]) + 0.45f*(vloadf(&g_sv[39+4*b])-vloadf(&g_sv[38+4*b]));
        float v = (g_La[idx]-q1)/(q9-q1+1e-8f);
        out[BN + idx] = fminf(fmaxf(v,0.f),1.f);   // output #2
    }
}

// ======================= host =======================
extern "C" void kernel_launch(void* const* d_in, const int* in_sizes, int n_in,
                              void* d_out, int out_size){
    const float* lab   = (const float*)d_in[0];
    const float* arand = (const float*)d_in[1];
    float* out = (float*)d_out;
    const int EB = (BN+255)/256;      // 1152 (exact)

    kSobelE<<<dim3(24,24,BB),256>>>(lab);
    kSolve<<<1,32>>>();
    kLperp<<<EB,256>>>(lab,out);

    selCoop<<<6*SELG,1024>>>(0,6);        // med+MAD of Lp,E,S
    kCovEighCdir<<<64,256>>>(arand);
    kKurtAcc<<<dim3(64,BB),256>>>();
    kKurtPick<<<1,32>>>();

    kPhaseZ<<<4*SELG,1024>>>();           // zb + quartile brackets
    kEM<<<EMB,1024>>>();                  // persistent EM -> Ra

    kClusterBin<<<dim3(64,BB),256>>>();
    kDMBoxH<<<dim3(576,4),256>>>();
    kBoxV<<<dim3(576,4),256>>>();
    kGLDTile<<<dim3(8,16,4),128>>>();

    selCoop<<<8*SELG,1024>>>(10,8);       // LLA + GLD med+MAD (merged)

    kFinalPhase<<<4*SELG,1024>>>(out);    // gamma/La + quantiles + normalize
}